// round 12
// baseline (speedup 1.0000x reference)
#include <cuda_runtime.h>
#include <cuda_bf16.h>
#include <cuda_fp8.h>
#include <math.h>
#include <cstdint>

#define NROWS 4096
#define DDIM  512
#define INV_TAU 5.0f
#define EXP_SCALE (INV_TAU / 256.0f)   // sim fp8 values scaled x16 -> dot x256
#define QSCL 16.0f
#define ZS 8.0f
#define WS 64.0f
#define TS 8.0f
#define DESC (1.0f / (ZS * WS))        // gemm descale 1/512
#define EPS_  1e-15f
#define L2EPS 1e-12f

#define NCHUNK 4
#define CHUNKJ (NROWS / NCHUNK)   // 1024
#define IT 128
#define NIB (NROWS / IT)          // 32

// sim kernel: 3-stage ring of 128-wide fp8 k-slabs, row stride 144B
#define S_AI 0
#define S_BI 18432
#define S_AJ 36864
#define S_BJ 46080
#define SIM_STAGE 55296
#define SIM_SMEM_BYTES (3 * SIM_STAGE + 8192)
#define NSTAGE 64          // 16 J-tiles x 4 slabs

// fp8 gemm kernel: 3-stage ring of 128-wide fp8 k-slabs, row stride 144B
#define GQ_STAGE 36864     // A 18432 + W 18432
#define GEMM_SMEM_BYTES (3 * GQ_STAGE)

typedef unsigned long long u64;

// ---------------- scratch (static device allocations; no cudaMalloc) ------
__device__ uint8_t g_za8[NROWS * DDIM];   // z1 fp8 x8
__device__ uint8_t g_zb8[NROWS * DDIM];   // z2 fp8 x8
__device__ uint8_t g_Ta8[NROWS * DDIM];   // T fp8 x8
__device__ uint8_t g_Tb8[NROWS * DDIM];
__device__ uint8_t g_w1q[DDIM * DDIM];    // lw1 fp8 x64
__device__ uint8_t g_w2q[DDIM * DDIM];
__device__ __nv_bfloat16 g_H16a[NROWS * DDIM];
__device__ __nv_bfloat16 g_H16b[NROWS * DDIM];
__device__ uint8_t g_a8[NROWS * DDIM];    // normalized h1 fp8 x16
__device__ uint8_t g_b8[NROWS * DDIM];    // normalized h2 fp8 x16
__device__ float g_gl[4 * NROWS];
__device__ float g_smp[2][16][DDIM];      // colmean partials
__device__ float g_summ[2 * DDIM];
__device__ float g_rp[NCHUNK][4][NROWS];  // row partials: aaS,aaM,abS,abM
__device__ float g_cp[4][NIB][NROWS];     // col partials: abS,abM,bbS,bbM

// ---------------- PTX helpers ----------------------------------------------
__device__ __forceinline__ uint32_t smem_u32(const void* p) {
    uint32_t a;
    asm("{ .reg .u64 tmp; cvta.to.shared.u64 tmp, %1; cvt.u32.u64 %0, tmp; }"
        : "=r"(a) : "l"(p));
    return a;
}

__device__ __forceinline__ void ldm4(uint32_t* r, uint32_t addr) {
    asm volatile("ldmatrix.sync.aligned.m8n8.x4.shared.b16 {%0,%1,%2,%3}, [%4];"
                 : "=r"(r[0]), "=r"(r[1]), "=r"(r[2]), "=r"(r[3]) : "r"(addr));
}

__device__ __forceinline__ void mma_fp8(float* c, const uint32_t* a,
                                        uint32_t b0, uint32_t b1) {
    asm volatile("mma.sync.aligned.m16n8k32.row.col.f32.e4m3.e4m3.f32 "
                 "{%0,%1,%2,%3}, {%4,%5,%6,%7}, {%8,%9}, {%0,%1,%2,%3};"
                 : "+f"(c[0]), "+f"(c[1]), "+f"(c[2]), "+f"(c[3])
                 : "r"(a[0]), "r"(a[1]), "r"(a[2]), "r"(a[3]), "r"(b0), "r"(b1));
}

__device__ __forceinline__ void cpa16(uint32_t dst, const void* src) {
    asm volatile("cp.async.cg.shared.global [%0], [%1], 16;"
                 :: "r"(dst), "l"(src) : "memory");
}
#define CP_COMMIT() asm volatile("cp.async.commit_group;" ::: "memory")
template <int N>
__device__ __forceinline__ void cp_wait() {
    asm volatile("cp.async.wait_group %0;" :: "n"(N) : "memory");
}

__device__ __forceinline__ uint32_t pack_fp8x4(float a, float b, float c, float d)
{
    __nv_fp8x2_storage_t lo = __nv_cvt_float2_to_fp8x2(
        make_float2(a, b), __NV_SATFINITE, __NV_E4M3);
    __nv_fp8x2_storage_t hi = __nv_cvt_float2_to_fp8x2(
        make_float2(c, d), __NV_SATFINITE, __NV_E4M3);
    return (uint32_t)lo | ((uint32_t)hi << 16);
}

// ---------------- fused conversion + colmean --------------------------------
#define ZN (NROWS * DDIM / 4)      // 524288 float4 groups
#define WN (DDIM * DDIM / 4)       // 65536
#define CTOT (2 * ZN + 2 * WN)

__global__ __launch_bounds__(256) void conv_all_kernel(
    const float* __restrict__ z1, const float* __restrict__ z2,
    const float* __restrict__ w1, const float* __restrict__ w2)
{
    if (blockIdx.x < 2048) {
        for (int i = blockIdx.x * 256 + threadIdx.x; i < CTOT; i += 2048 * 256) {
            const float* src;
            uint8_t* dst;
            float sc;
            int o;
            if (i < ZN)            { src = z1; dst = g_za8; sc = ZS; o = i; }
            else if (i < 2 * ZN)   { src = z2; dst = g_zb8; sc = ZS; o = i - ZN; }
            else if (i < 2*ZN+WN)  { src = w1; dst = g_w1q; sc = WS; o = i - 2*ZN; }
            else                   { src = w2; dst = g_w2q; sc = WS; o = i - 2*ZN - WN; }
            float4 v = ((const float4*)src)[o];
            ((uint32_t*)dst)[o] = pack_fp8x4(v.x * sc, v.y * sc, v.z * sc, v.w * sc);
        }
    } else {
        // colmean partials: 32 blocks, each 256 rows x (2 cols per thread)
        int b2 = blockIdx.x - 2048;
        int view = b2 >> 4, rb = b2 & 15;
        const float* z = view ? z2 : z1;
        const int r0 = rb * 256;
        for (int cc = threadIdx.x; cc < DDIM; cc += 256) {
            float a0 = 0, a1 = 0, a2 = 0, a3 = 0;
            for (int r = r0; r < r0 + 256; r += 4) {
                a0 += z[(size_t)(r+0) * DDIM + cc];
                a1 += z[(size_t)(r+1) * DDIM + cc];
                a2 += z[(size_t)(r+2) * DDIM + cc];
                a3 += z[(size_t)(r+3) * DDIM + cc];
            }
            g_smp[view][rb][cc] = (a0 + a1 + a2 + a3) * (1.0f / NROWS);
        }
    }
}

// ---------------- FP8 projector GEMM (512 threads, 3-stage ring) ------------
// C[4096,512] = A @ W^T (descale 1/512) + bias, optional PReLU.
// stage 1: A=g_z{a,b}8, W=g_w1q, out = g_T{a,b}8 (fp8 x8)
// stage 2: A=g_T{a,b}8, W=g_w2q, out = g_H16{a,b} (bf16)
// Warp w: rows (w&7)*16..+15, column half (w>>3)*64..+63 of 128x128 tile.
__global__ __launch_bounds__(512, 1) void gemm_fp8_kernel(
    const float* __restrict__ bias, const float* __restrict__ prelu_a, int stage)
{
    extern __shared__ __align__(16) char gsm[];
    const uint32_t u0 = smem_u32(gsm);

    const int t = threadIdx.x, w = t >> 5, lane = t & 31;
    const int rw = w & 7, chh = w >> 3;
    const int I0 = blockIdx.x * 128, J0 = blockIdx.y * 128;
    const int z = blockIdx.z;

    const uint8_t* __restrict__ A =
        (stage == 1) ? (z ? g_zb8 : g_za8) : (z ? g_Tb8 : g_Ta8);
    const uint8_t* __restrict__ Wq = (stage == 1) ? g_w1q : g_w2q;

    const int lr16 = lane & 15, lh = lane >> 4;
    const uint32_t aoff = (rw * 16 + lr16) * 144 + lh * 16;
    uint32_t boff[4];
    #pragma unroll
    for (int p = 0; p < 4; p++)
        boff[p] = ((chh * 4 + p) * 16 + lr16) * 144 + lh * 16;

    // cp.async mapping: A, W each 1024 16B-chunks per stage; 2 per thread
    int rI[2], cI[2];
    uint32_t dI[2];
    #pragma unroll
    for (int q = 0; q < 2; q++) {
        int id = t + q * 512;
        rI[q] = id >> 3; cI[q] = (id & 7) * 16;
        dI[q] = rI[q] * 144 + cI[q];
    }

    float acc[4][2][4];
    #pragma unroll
    for (int p = 0; p < 4; p++)
        #pragma unroll
        for (int h = 0; h < 2; h++)
            #pragma unroll
            for (int q = 0; q < 4; q++) acc[p][h][q] = 0.0f;

    #pragma unroll
    for (int s = 0; s < 2; s++) {
        const uint32_t b = u0 + s * GQ_STAGE;
        const int kb = s * 128;
        #pragma unroll
        for (int q = 0; q < 2; q++) {
            cpa16(b + dI[q], A + (size_t)(I0 + rI[q]) * DDIM + kb + cI[q]);
            cpa16(b + 18432 + dI[q], Wq + (size_t)(J0 + rI[q]) * DDIM + kb + cI[q]);
        }
        CP_COMMIT();
    }

    for (int ck = 0; ck < 4; ck++) {
        cp_wait<1>();
        __syncthreads();
        if (ck + 2 < 4) {
            const uint32_t b = u0 + ((ck + 2) % 3) * GQ_STAGE;
            const int kb = (ck + 2) * 128;
            #pragma unroll
            for (int q = 0; q < 2; q++) {
                cpa16(b + dI[q], A + (size_t)(I0 + rI[q]) * DDIM + kb + cI[q]);
                cpa16(b + 18432 + dI[q], Wq + (size_t)(J0 + rI[q]) * DDIM + kb + cI[q]);
            }
        }
        CP_COMMIT();
        const uint32_t uA = u0 + (ck % 3) * GQ_STAGE;
        const uint32_t uW = uA + 18432;
        #pragma unroll
        for (int ks = 0; ks < 4; ks++) {
            uint32_t fA[4];
            ldm4(fA, uA + aoff + ks * 32);
            #pragma unroll
            for (int p = 0; p < 4; p++) {
                uint32_t fW[4];
                ldm4(fW, uW + boff[p] + ks * 32);
                mma_fp8(acc[p][0], fA, fW[0], fW[2]);
                mma_fp8(acc[p][1], fA, fW[1], fW[3]);
            }
        }
    }

    const int er = lane >> 2, ec = 2 * (lane & 3);
    const int row = I0 + rw * 16 + er;
    const bool do_prelu = (prelu_a != nullptr);
    const float pa = do_prelu ? prelu_a[0] : 0.0f;

    uint8_t* Out8 = z ? g_Tb8 : g_Ta8;
    __nv_bfloat16* Out16 = z ? g_H16b : g_H16a;

    #pragma unroll
    for (int p = 0; p < 4; p++) {
        #pragma unroll
        for (int h = 0; h < 2; h++) {
            int col = J0 + chh * 64 + p * 16 + h * 8 + ec;
            float b0 = bias[col], b1 = bias[col + 1];
            float v0 = acc[p][h][0] * DESC + b0, v1 = acc[p][h][1] * DESC + b1;
            float v2 = acc[p][h][2] * DESC + b0, v3 = acc[p][h][3] * DESC + b1;
            if (do_prelu) {
                v0 = (v0 >= 0.0f) ? v0 : pa * v0;
                v1 = (v1 >= 0.0f) ? v1 : pa * v1;
                v2 = (v2 >= 0.0f) ? v2 : pa * v2;
                v3 = (v3 >= 0.0f) ? v3 : pa * v3;
            }
            if (stage == 1) {
                __nv_fp8x2_storage_t q0 = __nv_cvt_float2_to_fp8x2(
                    make_float2(v0 * TS, v1 * TS), __NV_SATFINITE, __NV_E4M3);
                __nv_fp8x2_storage_t q1 = __nv_cvt_float2_to_fp8x2(
                    make_float2(v2 * TS, v3 * TS), __NV_SATFINITE, __NV_E4M3);
                *(uint16_t*)(Out8 + (size_t)row * DDIM + col) = (uint16_t)q0;
                *(uint16_t*)(Out8 + (size_t)(row + 8) * DDIM + col) = (uint16_t)q1;
            } else {
                *(__nv_bfloat162*)(Out16 + (size_t)row * DDIM + col) =
                    __float22bfloat162_rn(make_float2(v0, v1));
                *(__nv_bfloat162*)(Out16 + (size_t)(row + 8) * DDIM + col) =
                    __float22bfloat162_rn(make_float2(v2, v3));
            }
        }
    }
}

// ---------------- row L2 normalization (bf16 in -> fp8 e4m3 out, x16) ------
__global__ __launch_bounds__(128) void l2norm_kernel()
{
    const __nv_bfloat16* h = blockIdx.y ? g_H16b : g_H16a;
    uint8_t* o8 = blockIdx.y ? g_b8 : g_a8;
    const int row = blockIdx.x;
    const int t = threadIdx.x;
    const __nv_bfloat162* src = (const __nv_bfloat162*)&h[(size_t)row * DDIM + t*4];
    __nv_bfloat162 h0 = src[0], h1 = src[1];
    float2 f0 = __bfloat1622float2(h0), f1 = __bfloat1622float2(h1);
    float ss = f0.x*f0.x + f0.y*f0.y + f1.x*f1.x + f1.y*f1.y;
    #pragma unroll
    for (int off = 16; off; off >>= 1) ss += __shfl_down_sync(0xffffffffu, ss, off);
    __shared__ float sm[4];
    __shared__ float stot;
    if ((t & 31) == 0) sm[t >> 5] = ss;
    __syncthreads();
    if (t == 0) stot = sm[0] + sm[1] + sm[2] + sm[3];
    __syncthreads();
    float scale = QSCL / fmaxf(sqrtf(stot), L2EPS);
    *(uint32_t*)(o8 + (size_t)row * DDIM + t * 4) =
        pack_fp8x4(f0.x * scale, f0.y * scale, f1.x * scale, f1.y * scale);
}

// ---------------- FP8 similarity kernel (512 threads, 16 warps) -------------
// CTA (Ib, c): I-rows Ib*128..+127; 16 J-tiles of 64 in chunk c, 4 slabs each.
// Warp w: rows (w&7)*16..+15, column half (w>>3)*32..+31 of each J-tile.
__global__ __launch_bounds__(512, 1) void sim_kernel(const int* __restrict__ mask)
{
    extern __shared__ __align__(16) char dsm[];
    const uint32_t u0 = smem_u32(dsm);
    float* sred = (float*)(dsm + 3 * SIM_STAGE);   // 2048 floats

    const int t = threadIdx.x, w = t >> 5, lane = t & 31;
    const int rw = w & 7, ch = w >> 3;
    const int Ib = blockIdx.x, c = blockIdx.y;
    const int I = Ib * IT;
    const int Jbase = c * CHUNKJ;

    const int lr16 = lane & 15, lh = lane >> 4;
    const uint32_t aoff = (rw * 16 + lr16) * 144 + lh * 16;
    uint32_t boff[2];
    #pragma unroll
    for (int p = 0; p < 2; p++)
        boff[p] = ((ch * 2 + p) * 16 + lr16) * 144 + lh * 16;

    int rI[2], cI[2];
    uint32_t dI[2];
    #pragma unroll
    for (int q = 0; q < 2; q++) {
        int id = t + q * 512;
        rI[q] = id >> 3; cI[q] = (id & 7) * 16;
        dI[q] = rI[q] * 144 + cI[q];
    }

    const int er = lane >> 2;
    const int ec = 2 * (lane & 3);
    const size_t gr0 = (size_t)(I + rw * 16 + er);

    float rs_aa0 = 0, rs_aa1 = 0, rm_aa0 = 0, rm_aa1 = 0;
    float rs_ab0 = 0, rs_ab1 = 0, rm_ab0 = 0, rm_ab1 = 0;

    float acc[3][4][4];
    #pragma unroll
    for (int m = 0; m < 3; m++)
        #pragma unroll
        for (int nb = 0; nb < 4; nb++)
            #pragma unroll
            for (int q = 0; q < 4; q++) acc[m][nb][q] = 0.0f;

    #define SIM_ISSUE(sidx)                                                     \
    do {                                                                        \
        const int _s = (sidx);                                                  \
        const uint32_t _b = u0 + (_s % 3) * SIM_STAGE;                          \
        const int _J0 = Jbase + (_s >> 2) * 64;                                 \
        const int _kb = (_s & 3) * 128;                                         \
        _Pragma("unroll")                                                       \
        for (int q = 0; q < 2; q++) {                                           \
            cpa16(_b + S_AI + dI[q], g_a8 + (size_t)(I + rI[q]) * DDIM + _kb + cI[q]); \
            cpa16(_b + S_BI + dI[q], g_b8 + (size_t)(I + rI[q]) * DDIM + _kb + cI[q]); \
        }                                                                       \
        cpa16(_b + S_AJ + dI[0], g_a8 + (size_t)(_J0 + rI[0]) * DDIM + _kb + cI[0]); \
        cpa16(_b + S_BJ + dI[0], g_b8 + (size_t)(_J0 + rI[0]) * DDIM + _kb + cI[0]); \
    } while (0)

    SIM_ISSUE(0); CP_COMMIT();
    SIM_ISSUE(1); CP_COMMIT();

    for (int s = 0; s < NSTAGE; s++) {
        cp_wait<1>();
        __syncthreads();
        if (s + 2 < NSTAGE) SIM_ISSUE(s + 2);
        CP_COMMIT();

        const uint32_t bc = u0 + (s % 3) * SIM_STAGE;
        const uint32_t uAI = bc + S_AI, uBI = bc + S_BI;
        const uint32_t uAJ = bc + S_AJ, uBJ = bc + S_BJ;
        #pragma unroll
        for (int ks = 0; ks < 4; ks++) {
            uint32_t fA[4], fB[4], fJA[2][4], fJB[2][4];
            ldm4(fA, uAI + aoff + ks * 32);
            ldm4(fB, uBI + aoff + ks * 32);
            #pragma unroll
            for (int p = 0; p < 2; p++) {
                ldm4(fJA[p], uAJ + boff[p] + ks * 32);
                ldm4(fJB[p], uBJ + boff[p] + ks * 32);
            }
            #pragma unroll
            for (int p = 0; p < 2; p++) {
                mma_fp8(acc[0][2*p],   fA, fJA[p][0], fJA[p][2]);
                mma_fp8(acc[0][2*p+1], fA, fJA[p][1], fJA[p][3]);
                mma_fp8(acc[1][2*p],   fA, fJB[p][0], fJB[p][2]);
                mma_fp8(acc[1][2*p+1], fA, fJB[p][1], fJB[p][3]);
                mma_fp8(acc[2][2*p],   fB, fJB[p][0], fJB[p][2]);
                mma_fp8(acc[2][2*p+1], fB, fJB[p][1], fJB[p][3]);
            }
        }

        if ((s & 3) == 3) {
            const int J0 = Jbase + (s >> 2) * 64;
            #pragma unroll
            for (int nb = 0; nb < 4; nb++) {
                const int gc = J0 + (ch * 4 + nb) * 8 + ec;
                int2 m0 = *(const int2*)(mask + gr0 * NROWS + gc);
                int2 m1 = *(const int2*)(mask + (gr0 + 8) * NROWS + gc);
                float m00 = (float)m0.x, m01 = (float)m0.y;
                float m10 = (float)m1.x, m11 = (float)m1.y;

                float ea0 = __expf(acc[0][nb][0] * EXP_SCALE);
                float ea1 = __expf(acc[0][nb][1] * EXP_SCALE);
                float ea2 = __expf(acc[0][nb][2] * EXP_SCALE);
                float ea3 = __expf(acc[0][nb][3] * EXP_SCALE);
                float eb0 = __expf(acc[1][nb][0] * EXP_SCALE);
                float eb1 = __expf(acc[1][nb][1] * EXP_SCALE);
                float eb2 = __expf(acc[1][nb][2] * EXP_SCALE);
                float eb3 = __expf(acc[1][nb][3] * EXP_SCALE);
                float ec0 = __expf(acc[2][nb][0] * EXP_SCALE);
                float ec1 = __expf(acc[2][nb][1] * EXP_SCALE);
                float ec2 = __expf(acc[2][nb][2] * EXP_SCALE);
                float ec3 = __expf(acc[2][nb][3] * EXP_SCALE);

                rs_aa0 += ea0 + ea1;  rm_aa0 += ea0 * m00 + ea1 * m01;
                rs_aa1 += ea2 + ea3;  rm_aa1 += ea2 * m10 + ea3 * m11;
                rs_ab0 += eb0 + eb1;  rm_ab0 += eb0 * m00 + eb1 * m01;
                rs_ab1 += eb2 + eb3;  rm_ab1 += eb2 * m10 + eb3 * m11;

                float v[8];
                v[0] = eb0 + eb2;              v[1] = eb1 + eb3;
                v[2] = eb0 * m00 + eb2 * m10;  v[3] = eb1 * m01 + eb3 * m11;
                v[4] = ec0 + ec2;              v[5] = ec1 + ec3;
                v[6] = ec0 * m00 + ec2 * m10;  v[7] = ec1 * m01 + ec3 * m11;
                #pragma unroll
                for (int q = 0; q < 8; q++) {
                    v[q] += __shfl_down_sync(0xffffffffu, v[q], 16);
                    v[q] += __shfl_down_sync(0xffffffffu, v[q], 8);
                    v[q] += __shfl_down_sync(0xffffffffu, v[q], 4);
                }
                if (lane < 4) {
                    int cl = nb * 8 + 2 * lane;
                    sred[w * 128 + 0 * 32 + cl]     = v[0];
                    sred[w * 128 + 0 * 32 + cl + 1] = v[1];
                    sred[w * 128 + 1 * 32 + cl]     = v[2];
                    sred[w * 128 + 1 * 32 + cl + 1] = v[3];
                    sred[w * 128 + 2 * 32 + cl]     = v[4];
                    sred[w * 128 + 2 * 32 + cl + 1] = v[5];
                    sred[w * 128 + 3 * 32 + cl]     = v[6];
                    sred[w * 128 + 3 * 32 + cl + 1] = v[7];
                }
            }
            __syncthreads();
            if (t < 256) {
                int q = t >> 6, colg = t & 63;
                int ch2 = colg >> 5, cl = colg & 31;
                float sacc = 0.0f;
                #pragma unroll
                for (int r2 = 0; r2 < 8; r2++)
                    sacc += sred[(ch2 * 8 + r2) * 128 + q * 32 + cl];
                g_cp[q][Ib][J0 + colg] = sacc;
            }
            #pragma unroll
            for (int m = 0; m < 3; m++)
                #pragma unroll
                for (int nb = 0; nb < 4; nb++)
                    #pragma unroll
                    for (int q = 0; q < 4; q++) acc[m][nb][q] = 0.0f;
        }
    }

    #pragma unroll
    for (int d = 1; d < 4; d <<= 1) {
        rs_aa0 += __shfl_down_sync(0xffffffffu, rs_aa0, d, 4);
        rs_aa1 += __shfl_down_sync(0xffffffffu, rs_aa1, d, 4);
        rm_aa0 += __shfl_down_sync(0xffffffffu, rm_aa0, d, 4);
        rm_aa1 += __shfl_down_sync(0xffffffffu, rm_aa1, d, 4);
        rs_ab0 += __shfl_down_sync(0xffffffffu, rs_ab0, d, 4);
        rs_ab1 += __shfl_down_sync(0xffffffffu, rs_ab1, d, 4);
        rm_ab0 += __shfl_down_sync(0xffffffffu, rm_ab0, d, 4);
        rm_ab1 += __shfl_down_sync(0xffffffffu, rm_ab1, d, 4);
    }
    __syncthreads();
    const int r0 = rw * 16 + er;
    if (ch == 1 && (lane & 3) == 0) {
        sred[r0 * 4 + 0] = rs_aa0;  sred[r0 * 4 + 1] = rm_aa0;
        sred[r0 * 4 + 2] = rs_ab0;  sred[r0 * 4 + 3] = rm_ab0;
        sred[(r0 + 8) * 4 + 0] = rs_aa1;  sred[(r0 + 8) * 4 + 1] = rm_aa1;
        sred[(r0 + 8) * 4 + 2] = rs_ab1;  sred[(r0 + 8) * 4 + 3] = rm_ab1;
    }
    __syncthreads();
    if (ch == 0 && (lane & 3) == 0) {
        g_rp[c][0][I + r0]     = rs_aa0 + sred[r0 * 4 + 0];
        g_rp[c][1][I + r0]     = rm_aa0 + sred[r0 * 4 + 1];
        g_rp[c][2][I + r0]     = rs_ab0 + sred[r0 * 4 + 2];
        g_rp[c][3][I + r0]     = rm_ab0 + sred[r0 * 4 + 3];
        g_rp[c][0][I + r0 + 8] = rs_aa1 + sred[(r0 + 8) * 4 + 0];
        g_rp[c][1][I + r0 + 8] = rm_aa1 + sred[(r0 + 8) * 4 + 1];
        g_rp[c][2][I + r0 + 8] = rs_ab1 + sred[(r0 + 8) * 4 + 2];
        g_rp[c][3][I + r0 + 8] = rm_ab1 + sred[(r0 + 8) * 4 + 3];
    }
}

// ---------------- global projector chain: summ_p = W @ proj(s_p) -----------
__device__ __forceinline__ void mv_stage(const float* __restrict__ Wm,
                                         const float* __restrict__ bias,
                                         const float* vin, float* vout,
                                         float pa, bool prelu_on,
                                         int warp, int lane)
{
    for (int rr = 0; rr < 32; rr++) {
        int o = warp * 32 + rr;
        const float* wr = Wm + (size_t)o * DDIM;
        float acc = 0.0f;
        for (int i = lane; i < DDIM; i += 32) acc += wr[i] * vin[i];
        #pragma unroll
        for (int off = 16; off; off >>= 1) acc += __shfl_down_sync(0xffffffffu, acc, off);
        if (lane == 0) {
            float v = acc + (bias ? bias[o] : 0.0f);
            if (prelu_on) v = (v >= 0.0f) ? v : pa * v;
            vout[o] = v;
        }
    }
}

__global__ __launch_bounds__(512) void gproj_kernel(
    const float* __restrict__ gw1, const float* __restrict__ gb1,
    const float* __restrict__ ga,  const float* __restrict__ gw2,
    const float* __restrict__ gb2, const float* __restrict__ W)
{
    __shared__ float v[DDIM], u[DDIM], hh[DDIM];
    const int p = blockIdx.x;
    const int t = threadIdx.x, warp = t >> 5, lane = t & 31;
    float sv = 0.0f;
    #pragma unroll
    for (int rb = 0; rb < 16; rb++) sv += g_smp[p][rb][t];
    v[t] = sv;
    __syncthreads();
    mv_stage(gw1, gb1, v, u, ga[0], true, warp, lane);
    __syncthreads();
    mv_stage(gw2, gb2, u, hh, 0.0f, false, warp, lane);
    __syncthreads();
    for (int rr = 0; rr < 32; rr++) {
        int o = warp * 32 + rr;
        const float* wr = W + (size_t)o * DDIM;
        float acc = 0.0f;
        for (int i = lane; i < DDIM; i += 32) acc += wr[i] * hh[i];
        #pragma unroll
        for (int off = 16; off; off >>= 1) acc += __shfl_down_sync(0xffffffffu, acc, off);
        if (lane == 0) g_summ[p * DDIM + o] = acc;
    }
}

// ---------------- per-row discriminator terms ------------------------------
__global__ __launch_bounds__(256) void sigrows_kernel(const float* __restrict__ z1,
                                                      const float* __restrict__ z2)
{
    const int warp = threadIdx.x >> 5, lane = threadIdx.x & 31;
    const int row = blockIdx.x * 8 + warp;
    const float* r1 = z1 + (size_t)row * DDIM;
    const float* r2 = z2 + (size_t)row * DDIM;
    float d11 = 0, d12 = 0, d21 = 0, d22 = 0;
    for (int i = lane; i < DDIM; i += 32) {
        float a = r1[i], b = r2[i];
        float s1 = g_summ[i], s2 = g_summ[DDIM + i];
        d11 += a * s1; d12 += a * s2; d21 += b * s1; d22 += b * s2;
    }
    #pragma unroll
    for (int off = 16; off; off >>= 1) {
        d11 += __shfl_down_sync(0xffffffffu, d11, off);
        d12 += __shfl_down_sync(0xffffffffu, d12, off);
        d21 += __shfl_down_sync(0xffffffffu, d21, off);
        d22 += __shfl_down_sync(0xffffffffu, d22, off);
    }
    if (lane == 0) {
        float sg11 = 1.0f / (1.0f + expf(-d11));
        float sg21 = 1.0f / (1.0f + expf(-d21));
        float sg22 = 1.0f / (1.0f + expf(-d22));
        float sg12 = 1.0f / (1.0f + expf(-d12));
        g_gl[0 * NROWS + row] = -logf(sg11 + EPS_);
        g_gl[1 * NROWS + row] = -logf(1.0f - sg21 + EPS_);
        g_gl[2 * NROWS + row] = -logf(sg22 + EPS_);
        g_gl[3 * NROWS + row] = -logf(1.0f - sg12 + EPS_);
    }
}

// ---------------- final reduction (rowloss fused) ---------------------------
__global__ __launch_bounds__(1024) void finalize_kernel(float* __restrict__ out)
{
    __shared__ float red[32];
    float acc[6] = {0, 0, 0, 0, 0, 0};
    for (int i = threadIdx.x; i < NROWS; i += 1024) {
        float aas = 0, aam = 0, abs_ = 0, abm = 0;
        #pragma unroll
        for (int c = 0; c < NCHUNK; c++) {
            aas  += g_rp[c][0][i];
            aam  += g_rp[c][1][i];
            abs_ += g_rp[c][2][i];
            abm  += g_rp[c][3][i];
        }
        float cabs = 0, cabm = 0, cbbs = 0, cbbm = 0;
        for (int b = 0; b < NIB; b++) {
            cabs += g_cp[0][b][i];
            cabm += g_cp[1][b][i];
            cbbs += g_cp[2][b][i];
            cbbm += g_cp[3][b][i];
        }
        acc[0] += -logf(abm / (aas + abs_ - aam));
        acc[1] += -logf(cabm / (cbbs + cabs - cbbm));
        acc[2] += g_gl[i];
        acc[3] += g_gl[NROWS + i];
        acc[4] += g_gl[2 * NROWS + i];
        acc[5] += g_gl[3 * NROWS + i];
    }
    const int lane = threadIdx.x & 31, warp = threadIdx.x >> 5;
    float tot[6];
    for (int q = 0; q < 6; q++) {
        float v = acc[q];
        #pragma unroll
        for (int off = 16; off; off >>= 1) v += __shfl_down_sync(0xffffffffu, v, off);
        if (lane == 0) red[warp] = v;
        __syncthreads();
        if (warp == 0) {
            float w = red[lane];
            #pragma unroll
            for (int off = 16; off; off >>= 1) w += __shfl_down_sync(0xffffffffu, w, off);
            if (lane == 0) tot[q] = w;
        }
        __syncthreads();
    }
    if (threadIdx.x == 0) {
        const float inv = 1.0f / NROWS;
        float local = 0.5f * (tot[0] + tot[1]) * inv;
        float gl1   = 0.5f * (tot[2] + tot[3]) * inv;
        float gl2   = 0.5f * (tot[4] + tot[5]) * inv;
        float glob  = 0.5f * (gl1 + gl2);
        out[0] = 0.5f * local + 0.5f * glob;   // ALPHA = 0.5
    }
}

// ---------------- launch ----------------------------------------------------
extern "C" void kernel_launch(void* const* d_in, const int* in_sizes, int n_in,
                              void* d_out, int out_size)
{
    const float* z1  = (const float*)d_in[0];
    const float* z2  = (const float*)d_in[1];
    const float* lw1 = (const float*)d_in[2];
    const float* lb1 = (const float*)d_in[3];
    const float* la  = (const float*)d_in[4];
    const float* lw2 = (const float*)d_in[5];
    const float* lb2 = (const float*)d_in[6];
    const float* gw1 = (const float*)d_in[7];
    const float* gb1 = (const float*)d_in[8];
    const float* ga  = (const float*)d_in[9];
    const float* gw2 = (const float*)d_in[10];
    const float* gb2 = (const float*)d_in[11];
    const float* W   = (const float*)d_in[12];
    const int*   mask= (const int*)  d_in[13];
    float* out = (float*)d_out;

    cudaFuncSetAttribute(sim_kernel, cudaFuncAttributeMaxDynamicSharedMemorySize,
                         SIM_SMEM_BYTES);
    cudaFuncSetAttribute(gemm_fp8_kernel, cudaFuncAttributeMaxDynamicSharedMemorySize,
                         GEMM_SMEM_BYTES);

    conv_all_kernel<<<2080, 256>>>(z1, z2, lw1, lw2);

    gemm_fp8_kernel<<<dim3(32, 4, 2), 512, GEMM_SMEM_BYTES>>>(lb1, la, 1);
    gemm_fp8_kernel<<<dim3(32, 4, 2), 512, GEMM_SMEM_BYTES>>>(lb2, nullptr, 2);

    l2norm_kernel<<<dim3(NROWS, 2), 128>>>();

    sim_kernel<<<dim3(NIB, NCHUNK), 512, SIM_SMEM_BYTES>>>(mask);

    gproj_kernel<<<2, DDIM>>>(gw1, gb1, ga, gw2, gb2, W);
    sigrows_kernel<<<NROWS / 8, 256>>>(z1, z2);

    finalize_kernel<<<1, 1024>>>(out);
}

// round 13
// speedup vs baseline: 1.3522x; 1.3522x over previous
#include <cuda_runtime.h>
#include <cuda_bf16.h>
#include <cuda_fp8.h>
#include <math.h>
#include <cstdint>

#define NROWS 4096
#define DDIM  512
#define INV_TAU 5.0f
#define EXP_SCALE (INV_TAU / 256.0f)   // fp8 values scaled x16 -> dot x256
#define QSCL 16.0f
#define EPS_  1e-15f
#define L2EPS 1e-12f

#define NCHUNK 4
#define CHUNKJ (NROWS / NCHUNK)   // 1024
#define IT 128
#define NIB (NROWS / IT)          // 32

// sim kernel: 3-stage ring of 128-wide fp8 k-slabs, row stride 144B
#define S_AI 0
#define S_BI 18432
#define S_AJ 36864
#define S_BJ 46080
#define SIM_STAGE 55296
#define SIM_SMEM_BYTES (3 * SIM_STAGE + 8192)
#define NSTAGE 64          // 16 J-tiles x 4 slabs

// gemm kernel: 3-stage ring of 32-wide bf16 k-slabs, row stride 80B
#define G_STAGE 20480
#define GEMM_SMEM_BYTES (3 * G_STAGE)

typedef unsigned long long u64;

// ---------------- scratch (static device allocations; no cudaMalloc) ------
__device__ __nv_bfloat16 g_z16a[NROWS * DDIM];
__device__ __nv_bfloat16 g_z16b[NROWS * DDIM];
__device__ __nv_bfloat16 g_T16a[NROWS * DDIM];
__device__ __nv_bfloat16 g_T16b[NROWS * DDIM];
__device__ __nv_bfloat16 g_H16a[NROWS * DDIM];
__device__ __nv_bfloat16 g_H16b[NROWS * DDIM];
__device__ __nv_bfloat16 g_w1s[DDIM * DDIM];
__device__ __nv_bfloat16 g_w2s[DDIM * DDIM];
__device__ uint8_t g_a8[NROWS * DDIM];   // fp8 e4m3, scaled x16
__device__ uint8_t g_b8[NROWS * DDIM];
__device__ float g_gl[4 * NROWS];
__device__ float g_smp[2][16][DDIM];      // colmean partials
__device__ float g_summ[2 * DDIM];
__device__ float g_rp[NCHUNK][4][NROWS];  // row partials: aaS,aaM,abS,abM
__device__ float g_cp[4][NIB][NROWS];     // col partials: abS,abM,bbS,bbM

// ---------------- PTX helpers ----------------------------------------------
__device__ __forceinline__ uint32_t smem_u32(const void* p) {
    uint32_t a;
    asm("{ .reg .u64 tmp; cvta.to.shared.u64 tmp, %1; cvt.u32.u64 %0, tmp; }"
        : "=r"(a) : "l"(p));
    return a;
}

__device__ __forceinline__ void ldm4(uint32_t* r, uint32_t addr) {
    asm volatile("ldmatrix.sync.aligned.m8n8.x4.shared.b16 {%0,%1,%2,%3}, [%4];"
                 : "=r"(r[0]), "=r"(r[1]), "=r"(r[2]), "=r"(r[3]) : "r"(addr));
}

__device__ __forceinline__ void mma16816(float* c, const uint32_t* a,
                                         uint32_t b0, uint32_t b1) {
    asm volatile("mma.sync.aligned.m16n8k16.row.col.f32.bf16.bf16.f32 "
                 "{%0,%1,%2,%3}, {%4,%5,%6,%7}, {%8,%9}, {%0,%1,%2,%3};"
                 : "+f"(c[0]), "+f"(c[1]), "+f"(c[2]), "+f"(c[3])
                 : "r"(a[0]), "r"(a[1]), "r"(a[2]), "r"(a[3]), "r"(b0), "r"(b1));
}

__device__ __forceinline__ void mma_fp8(float* c, const uint32_t* a,
                                        uint32_t b0, uint32_t b1) {
    asm volatile("mma.sync.aligned.m16n8k32.row.col.f32.e4m3.e4m3.f32 "
                 "{%0,%1,%2,%3}, {%4,%5,%6,%7}, {%8,%9}, {%0,%1,%2,%3};"
                 : "+f"(c[0]), "+f"(c[1]), "+f"(c[2]), "+f"(c[3])
                 : "r"(a[0]), "r"(a[1]), "r"(a[2]), "r"(a[3]), "r"(b0), "r"(b1));
}

__device__ __forceinline__ void cpa16(uint32_t dst, const void* src) {
    asm volatile("cp.async.cg.shared.global [%0], [%1], 16;"
                 :: "r"(dst), "l"(src) : "memory");
}
#define CP_COMMIT() asm volatile("cp.async.commit_group;" ::: "memory")
template <int N>
__device__ __forceinline__ void cp_wait() {
    asm volatile("cp.async.wait_group %0;" :: "n"(N) : "memory");
}

// ---------------- fused fp32 -> bf16 conversion + colmean partials ---------
#define Z4 (NROWS * DDIM / 4)      // 524288
#define W4 (DDIM * DDIM / 4)       // 65536
#define TOT4 (2 * Z4 + 2 * W4)

__global__ __launch_bounds__(256) void conv_all_kernel(
    const float* __restrict__ z1, const float* __restrict__ z2,
    const float* __restrict__ w1, const float* __restrict__ w2)
{
    if (blockIdx.x < 2048) {
        for (int i = blockIdx.x * 256 + threadIdx.x; i < TOT4; i += 2048 * 256) {
            const float* src;
            __nv_bfloat16* dst;
            int o;
            if (i < Z4)            { src = z1; dst = g_z16a; o = i; }
            else if (i < 2 * Z4)   { src = z2; dst = g_z16b; o = i - Z4; }
            else if (i < 2*Z4+W4)  { src = w1; dst = g_w1s;  o = i - 2*Z4; }
            else                   { src = w2; dst = g_w2s;  o = i - 2*Z4 - W4; }
            float4 v = ((const float4*)src)[o];
            __nv_bfloat162* d = (__nv_bfloat162*)(dst + (size_t)o * 4);
            d[0] = __float22bfloat162_rn(make_float2(v.x, v.y));
            d[1] = __float22bfloat162_rn(make_float2(v.z, v.w));
        }
    } else {
        // colmean partials: 32 blocks, each sums 256 rows
        int b2 = blockIdx.x - 2048;
        int view = b2 >> 4, rb = b2 & 15;
        const float* z = view ? z2 : z1;
        const int r0 = rb * 256;
        for (int cc = threadIdx.x; cc < DDIM; cc += 256) {
            float a0 = 0, a1 = 0, a2 = 0, a3 = 0;
            for (int r = r0; r < r0 + 256; r += 4) {
                a0 += z[(size_t)(r+0) * DDIM + cc];
                a1 += z[(size_t)(r+1) * DDIM + cc];
                a2 += z[(size_t)(r+2) * DDIM + cc];
                a3 += z[(size_t)(r+3) * DDIM + cc];
            }
            g_smp[view][rb][cc] = (a0 + a1 + a2 + a3) * (1.0f / NROWS);
        }
    }
}

// ---------------- HMMA projector GEMM (256 threads, 3-stage ring) -----------
__global__ __launch_bounds__(256, 1) void gemm_hmma_kernel(
    const float* __restrict__ bias, const float* __restrict__ prelu_a, int stage)
{
    extern __shared__ __align__(16) char gsm[];
    const uint32_t u0 = smem_u32(gsm);

    const int t = threadIdx.x, w = t >> 5, lane = t & 31;
    const int I0 = blockIdx.x * 128, J0 = blockIdx.y * 128;
    const int z = blockIdx.z;

    const __nv_bfloat16* __restrict__ A =
        (stage == 1) ? (z ? g_z16b : g_z16a) : (z ? g_T16b : g_T16a);
    const __nv_bfloat16* __restrict__ Wm = (stage == 1) ? g_w1s : g_w2s;

    const int lr16 = lane & 15, lh = lane >> 4;
    const uint32_t aoff = (w * 16 + lr16) * 80 + lh * 16;
    uint32_t boff[8];
    #pragma unroll
    for (int p = 0; p < 8; p++)
        boff[p] = (p * 16 + lr16) * 80 + lh * 16;

    int rr[2], cc8[2];
    uint32_t dd[2];
    #pragma unroll
    for (int q = 0; q < 2; q++) {
        int id = t + q * 256;
        rr[q] = id >> 2; cc8[q] = (id & 3) * 8;
        dd[q] = rr[q] * 80 + (id & 3) * 16;
    }

    float acc[8][2][4];
    #pragma unroll
    for (int p = 0; p < 8; p++)
        #pragma unroll
        for (int h = 0; h < 2; h++)
            #pragma unroll
            for (int q = 0; q < 4; q++) acc[p][h][q] = 0.0f;

    #pragma unroll
    for (int s = 0; s < 2; s++) {
        const uint32_t b = u0 + s * G_STAGE;
        const int kb = s * 32;
        #pragma unroll
        for (int q = 0; q < 2; q++) {
            cpa16(b + dd[q], A + (size_t)(I0 + rr[q]) * DDIM + kb + cc8[q]);
            cpa16(b + 10240 + dd[q], Wm + (size_t)(J0 + rr[q]) * DDIM + kb + cc8[q]);
        }
        CP_COMMIT();
    }

    for (int ck = 0; ck < 16; ck++) {
        cp_wait<1>();
        __syncthreads();
        if (ck + 2 < 16) {
            const uint32_t b = u0 + ((ck + 2) % 3) * G_STAGE;
            const int kb = (ck + 2) * 32;
            #pragma unroll
            for (int q = 0; q < 2; q++) {
                cpa16(b + dd[q], A + (size_t)(I0 + rr[q]) * DDIM + kb + cc8[q]);
                cpa16(b + 10240 + dd[q], Wm + (size_t)(J0 + rr[q]) * DDIM + kb + cc8[q]);
            }
        }
        CP_COMMIT();
        const uint32_t uA = u0 + (ck % 3) * G_STAGE;
        const uint32_t uW = uA + 10240;
        #pragma unroll
        for (int ks = 0; ks < 2; ks++) {
            uint32_t fA[4];
            ldm4(fA, uA + aoff + ks * 32);
            #pragma unroll
            for (int p = 0; p < 8; p++) {
                uint32_t fW[4];
                ldm4(fW, uW + boff[p] + ks * 32);
                mma16816(acc[p][0], fA, fW[0], fW[2]);
                mma16816(acc[p][1], fA, fW[1], fW[3]);
            }
        }
    }

    const int er = lane >> 2, ec = 2 * (lane & 3);
    const int row = I0 + w * 16 + er;
    const bool do_prelu = (prelu_a != nullptr);
    const float pa = do_prelu ? prelu_a[0] : 0.0f;

    __nv_bfloat16* Out = (stage == 1) ? (z ? g_T16b : g_T16a)
                                      : (z ? g_H16b : g_H16a);
    #pragma unroll
    for (int p = 0; p < 8; p++) {
        #pragma unroll
        for (int h = 0; h < 2; h++) {
            int col = J0 + p * 16 + h * 8 + ec;
            float b0 = bias[col], b1 = bias[col + 1];
            float v0 = acc[p][h][0] + b0, v1 = acc[p][h][1] + b1;
            float v2 = acc[p][h][2] + b0, v3 = acc[p][h][3] + b1;
            if (do_prelu) {
                v0 = (v0 >= 0.0f) ? v0 : pa * v0;
                v1 = (v1 >= 0.0f) ? v1 : pa * v1;
                v2 = (v2 >= 0.0f) ? v2 : pa * v2;
                v3 = (v3 >= 0.0f) ? v3 : pa * v3;
            }
            *(__nv_bfloat162*)(Out + (size_t)row * DDIM + col) =
                __float22bfloat162_rn(make_float2(v0, v1));
            *(__nv_bfloat162*)(Out + (size_t)(row + 8) * DDIM + col) =
                __float22bfloat162_rn(make_float2(v2, v3));
        }
    }
}

// ---------------- row L2 normalization (bf16 in -> fp8 e4m3 out, x16) ------
__global__ __launch_bounds__(128) void l2norm_kernel()
{
    const __nv_bfloat16* h = blockIdx.y ? g_H16b : g_H16a;
    uint8_t* o8 = blockIdx.y ? g_b8 : g_a8;
    const int row = blockIdx.x;
    const int t = threadIdx.x;
    const __nv_bfloat162* src = (const __nv_bfloat162*)&h[(size_t)row * DDIM + t*4];
    __nv_bfloat162 h0 = src[0], h1 = src[1];
    float2 f0 = __bfloat1622float2(h0), f1 = __bfloat1622float2(h1);
    float ss = f0.x*f0.x + f0.y*f0.y + f1.x*f1.x + f1.y*f1.y;
    #pragma unroll
    for (int off = 16; off; off >>= 1) ss += __shfl_down_sync(0xffffffffu, ss, off);
    __shared__ float sm[4];
    __shared__ float stot;
    if ((t & 31) == 0) sm[t >> 5] = ss;
    __syncthreads();
    if (t == 0) stot = sm[0] + sm[1] + sm[2] + sm[3];
    __syncthreads();
    float scale = QSCL / fmaxf(sqrtf(stot), L2EPS);
    __nv_fp8x2_storage_t lo = __nv_cvt_float2_to_fp8x2(
        make_float2(f0.x * scale, f0.y * scale), __NV_SATFINITE, __NV_E4M3);
    __nv_fp8x2_storage_t hi = __nv_cvt_float2_to_fp8x2(
        make_float2(f1.x * scale, f1.y * scale), __NV_SATFINITE, __NV_E4M3);
    uint32_t packed = (uint32_t)lo | ((uint32_t)hi << 16);
    *(uint32_t*)(o8 + (size_t)row * DDIM + t * 4) = packed;
}

// ---------------- FP8 similarity kernel (512 threads, 16 warps) -------------
__global__ __launch_bounds__(512, 1) void sim_kernel(const int* __restrict__ mask)
{
    extern __shared__ __align__(16) char dsm[];
    const uint32_t u0 = smem_u32(dsm);
    float* sred = (float*)(dsm + 3 * SIM_STAGE);   // 2048 floats

    const int t = threadIdx.x, w = t >> 5, lane = t & 31;
    const int rw = w & 7, ch = w >> 3;
    const int Ib = blockIdx.x, c = blockIdx.y;
    const int I = Ib * IT;
    const int Jbase = c * CHUNKJ;

    const int lr16 = lane & 15, lh = lane >> 4;
    const uint32_t aoff = (rw * 16 + lr16) * 144 + lh * 16;
    uint32_t boff[2];
    #pragma unroll
    for (int p = 0; p < 2; p++)
        boff[p] = ((ch * 2 + p) * 16 + lr16) * 144 + lh * 16;

    int rI[2], cI[2];
    uint32_t dI[2];
    #pragma unroll
    for (int q = 0; q < 2; q++) {
        int id = t + q * 512;
        rI[q] = id >> 3; cI[q] = (id & 7) * 16;
        dI[q] = rI[q] * 144 + cI[q];
    }

    const int er = lane >> 2;
    const int ec = 2 * (lane & 3);
    const size_t gr0 = (size_t)(I + rw * 16 + er);

    float rs_aa0 = 0, rs_aa1 = 0, rm_aa0 = 0, rm_aa1 = 0;
    float rs_ab0 = 0, rs_ab1 = 0, rm_ab0 = 0, rm_ab1 = 0;

    float acc[3][4][4];
    #pragma unroll
    for (int m = 0; m < 3; m++)
        #pragma unroll
        for (int nb = 0; nb < 4; nb++)
            #pragma unroll
            for (int q = 0; q < 4; q++) acc[m][nb][q] = 0.0f;

    #define SIM_ISSUE(sidx)                                                     \
    do {                                                                        \
        const int _s = (sidx);                                                  \
        const uint32_t _b = u0 + (_s % 3) * SIM_STAGE;                          \
        const int _J0 = Jbase + (_s >> 2) * 64;                                 \
        const int _kb = (_s & 3) * 128;                                         \
        _Pragma("unroll")                                                       \
        for (int q = 0; q < 2; q++) {                                           \
            cpa16(_b + S_AI + dI[q], g_a8 + (size_t)(I + rI[q]) * DDIM + _kb + cI[q]); \
            cpa16(_b + S_BI + dI[q], g_b8 + (size_t)(I + rI[q]) * DDIM + _kb + cI[q]); \
        }                                                                       \
        cpa16(_b + S_AJ + dI[0], g_a8 + (size_t)(_J0 + rI[0]) * DDIM + _kb + cI[0]); \
        cpa16(_b + S_BJ + dI[0], g_b8 + (size_t)(_J0 + rI[0]) * DDIM + _kb + cI[0]); \
    } while (0)

    SIM_ISSUE(0); CP_COMMIT();
    SIM_ISSUE(1); CP_COMMIT();

    for (int s = 0; s < NSTAGE; s++) {
        cp_wait<1>();
        __syncthreads();
        if (s + 2 < NSTAGE) SIM_ISSUE(s + 2);
        CP_COMMIT();

        const uint32_t bc = u0 + (s % 3) * SIM_STAGE;
        const uint32_t uAI = bc + S_AI, uBI = bc + S_BI;
        const uint32_t uAJ = bc + S_AJ, uBJ = bc + S_BJ;
        #pragma unroll
        for (int ks = 0; ks < 4; ks++) {      // each ks = 32 fp8 k-elements
            uint32_t fA[4], fB[4], fJA[2][4], fJB[2][4];
            ldm4(fA, uAI + aoff + ks * 32);
            ldm4(fB, uBI + aoff + ks * 32);
            #pragma unroll
            for (int p = 0; p < 2; p++) {
                ldm4(fJA[p], uAJ + boff[p] + ks * 32);
                ldm4(fJB[p], uBJ + boff[p] + ks * 32);
            }
            #pragma unroll
            for (int p = 0; p < 2; p++) {
                mma_fp8(acc[0][2*p],   fA, fJA[p][0], fJA[p][2]);
                mma_fp8(acc[0][2*p+1], fA, fJA[p][1], fJA[p][3]);
                mma_fp8(acc[1][2*p],   fA, fJB[p][0], fJB[p][2]);
                mma_fp8(acc[1][2*p+1], fA, fJB[p][1], fJB[p][3]);
                mma_fp8(acc[2][2*p],   fB, fJB[p][0], fJB[p][2]);
                mma_fp8(acc[2][2*p+1], fB, fJB[p][1], fJB[p][3]);
            }
        }

        if ((s & 3) == 3) {
            const int J0 = Jbase + (s >> 2) * 64;
            #pragma unroll
            for (int nb = 0; nb < 4; nb++) {
                const int gc = J0 + (ch * 4 + nb) * 8 + ec;
                int2 m0 = *(const int2*)(mask + gr0 * NROWS + gc);
                int2 m1 = *(const int2*)(mask + (gr0 + 8) * NROWS + gc);
                float m00 = (float)m0.x, m01 = (float)m0.y;
                float m10 = (float)m1.x, m11 = (float)m1.y;

                float ea0 = __expf(acc[0][nb][0] * EXP_SCALE);
                float ea1 = __expf(acc[0][nb][1] * EXP_SCALE);
                float ea2 = __expf(acc[0][nb][2] * EXP_SCALE);
                float ea3 = __expf(acc[0][nb][3] * EXP_SCALE);
                float eb0 = __expf(acc[1][nb][0] * EXP_SCALE);
                float eb1 = __expf(acc[1][nb][1] * EXP_SCALE);
                float eb2 = __expf(acc[1][nb][2] * EXP_SCALE);
                float eb3 = __expf(acc[1][nb][3] * EXP_SCALE);
                float ec0 = __expf(acc[2][nb][0] * EXP_SCALE);
                float ec1 = __expf(acc[2][nb][1] * EXP_SCALE);
                float ec2 = __expf(acc[2][nb][2] * EXP_SCALE);
                float ec3 = __expf(acc[2][nb][3] * EXP_SCALE);

                rs_aa0 += ea0 + ea1;  rm_aa0 += ea0 * m00 + ea1 * m01;
                rs_aa1 += ea2 + ea3;  rm_aa1 += ea2 * m10 + ea3 * m11;
                rs_ab0 += eb0 + eb1;  rm_ab0 += eb0 * m00 + eb1 * m01;
                rs_ab1 += eb2 + eb3;  rm_ab1 += eb2 * m10 + eb3 * m11;

                float v[8];
                v[0] = eb0 + eb2;              v[1] = eb1 + eb3;
                v[2] = eb0 * m00 + eb2 * m10;  v[3] = eb1 * m01 + eb3 * m11;
                v[4] = ec0 + ec2;              v[5] = ec1 + ec3;
                v[6] = ec0 * m00 + ec2 * m10;  v[7] = ec1 * m01 + ec3 * m11;
                #pragma unroll
                for (int q = 0; q < 8; q++) {
                    v[q] += __shfl_down_sync(0xffffffffu, v[q], 16);
                    v[q] += __shfl_down_sync(0xffffffffu, v[q], 8);
                    v[q] += __shfl_down_sync(0xffffffffu, v[q], 4);
                }
                if (lane < 4) {
                    int cl = nb * 8 + 2 * lane;
                    sred[w * 128 + 0 * 32 + cl]     = v[0];
                    sred[w * 128 + 0 * 32 + cl + 1] = v[1];
                    sred[w * 128 + 1 * 32 + cl]     = v[2];
                    sred[w * 128 + 1 * 32 + cl + 1] = v[3];
                    sred[w * 128 + 2 * 32 + cl]     = v[4];
                    sred[w * 128 + 2 * 32 + cl + 1] = v[5];
                    sred[w * 128 + 3 * 32 + cl]     = v[6];
                    sred[w * 128 + 3 * 32 + cl + 1] = v[7];
                }
            }
            __syncthreads();
            if (t < 256) {
                int q = t >> 6, colg = t & 63;
                int ch2 = colg >> 5, cl = colg & 31;
                float sacc = 0.0f;
                #pragma unroll
                for (int r2 = 0; r2 < 8; r2++)
                    sacc += sred[(ch2 * 8 + r2) * 128 + q * 32 + cl];
                g_cp[q][Ib][J0 + colg] = sacc;
            }
            #pragma unroll
            for (int m = 0; m < 3; m++)
                #pragma unroll
                for (int nb = 0; nb < 4; nb++)
                    #pragma unroll
                    for (int q = 0; q < 4; q++) acc[m][nb][q] = 0.0f;
        }
    }

    #pragma unroll
    for (int d = 1; d < 4; d <<= 1) {
        rs_aa0 += __shfl_down_sync(0xffffffffu, rs_aa0, d, 4);
        rs_aa1 += __shfl_down_sync(0xffffffffu, rs_aa1, d, 4);
        rm_aa0 += __shfl_down_sync(0xffffffffu, rm_aa0, d, 4);
        rm_aa1 += __shfl_down_sync(0xffffffffu, rm_aa1, d, 4);
        rs_ab0 += __shfl_down_sync(0xffffffffu, rs_ab0, d, 4);
        rs_ab1 += __shfl_down_sync(0xffffffffu, rs_ab1, d, 4);
        rm_ab0 += __shfl_down_sync(0xffffffffu, rm_ab0, d, 4);
        rm_ab1 += __shfl_down_sync(0xffffffffu, rm_ab1, d, 4);
    }
    __syncthreads();
    const int r0 = rw * 16 + er;
    if (ch == 1 && (lane & 3) == 0) {
        sred[r0 * 4 + 0] = rs_aa0;  sred[r0 * 4 + 1] = rm_aa0;
        sred[r0 * 4 + 2] = rs_ab0;  sred[r0 * 4 + 3] = rm_ab0;
        sred[(r0 + 8) * 4 + 0] = rs_aa1;  sred[(r0 + 8) * 4 + 1] = rm_aa1;
        sred[(r0 + 8) * 4 + 2] = rs_ab1;  sred[(r0 + 8) * 4 + 3] = rm_ab1;
    }
    __syncthreads();
    if (ch == 0 && (lane & 3) == 0) {
        g_rp[c][0][I + r0]     = rs_aa0 + sred[r0 * 4 + 0];
        g_rp[c][1][I + r0]     = rm_aa0 + sred[r0 * 4 + 1];
        g_rp[c][2][I + r0]     = rs_ab0 + sred[r0 * 4 + 2];
        g_rp[c][3][I + r0]     = rm_ab0 + sred[r0 * 4 + 3];
        g_rp[c][0][I + r0 + 8] = rs_aa1 + sred[(r0 + 8) * 4 + 0];
        g_rp[c][1][I + r0 + 8] = rm_aa1 + sred[(r0 + 8) * 4 + 1];
        g_rp[c][2][I + r0 + 8] = rs_ab1 + sred[(r0 + 8) * 4 + 2];
        g_rp[c][3][I + r0 + 8] = rm_ab1 + sred[(r0 + 8) * 4 + 3];
    }
}

// ---------------- global projector chain: summ_p = W @ proj(s_p) -----------
__device__ __forceinline__ void mv_stage(const float* __restrict__ Wm,
                                         const float* __restrict__ bias,
                                         const float* vin, float* vout,
                                         float pa, bool prelu_on,
                                         int warp, int lane)
{
    for (int rr = 0; rr < 32; rr++) {
        int o = warp * 32 + rr;
        const float* wr = Wm + (size_t)o * DDIM;
        float acc = 0.0f;
        for (int i = lane; i < DDIM; i += 32) acc += wr[i] * vin[i];
        #pragma unroll
        for (int off = 16; off; off >>= 1) acc += __shfl_down_sync(0xffffffffu, acc, off);
        if (lane == 0) {
            float v = acc + (bias ? bias[o] : 0.0f);
            if (prelu_on) v = (v >= 0.0f) ? v : pa * v;
            vout[o] = v;
        }
    }
}

__global__ __launch_bounds__(512) void gproj_kernel(
    const float* __restrict__ gw1, const float* __restrict__ gb1,
    const float* __restrict__ ga,  const float* __restrict__ gw2,
    const float* __restrict__ gb2, const float* __restrict__ W)
{
    __shared__ float v[DDIM], u[DDIM], hh[DDIM];
    const int p = blockIdx.x;
    const int t = threadIdx.x, warp = t >> 5, lane = t & 31;
    float sv = 0.0f;
    #pragma unroll
    for (int rb = 0; rb < 16; rb++) sv += g_smp[p][rb][t];
    v[t] = sv;
    __syncthreads();
    mv_stage(gw1, gb1, v, u, ga[0], true, warp, lane);
    __syncthreads();
    mv_stage(gw2, gb2, u, hh, 0.0f, false, warp, lane);
    __syncthreads();
    for (int rr = 0; rr < 32; rr++) {
        int o = warp * 32 + rr;
        const float* wr = W + (size_t)o * DDIM;
        float acc = 0.0f;
        for (int i = lane; i < DDIM; i += 32) acc += wr[i] * hh[i];
        #pragma unroll
        for (int off = 16; off; off >>= 1) acc += __shfl_down_sync(0xffffffffu, acc, off);
        if (lane == 0) g_summ[p * DDIM + o] = acc;
    }
}

// ---------------- per-row discriminator terms ------------------------------
__global__ __launch_bounds__(256) void sigrows_kernel(const float* __restrict__ z1,
                                                      const float* __restrict__ z2)
{
    const int warp = threadIdx.x >> 5, lane = threadIdx.x & 31;
    const int row = blockIdx.x * 8 + warp;
    const float* r1 = z1 + (size_t)row * DDIM;
    const float* r2 = z2 + (size_t)row * DDIM;
    float d11 = 0, d12 = 0, d21 = 0, d22 = 0;
    for (int i = lane; i < DDIM; i += 32) {
        float a = r1[i], b = r2[i];
        float s1 = g_summ[i], s2 = g_summ[DDIM + i];
        d11 += a * s1; d12 += a * s2; d21 += b * s1; d22 += b * s2;
    }
    #pragma unroll
    for (int off = 16; off; off >>= 1) {
        d11 += __shfl_down_sync(0xffffffffu, d11, off);
        d12 += __shfl_down_sync(0xffffffffu, d12, off);
        d21 += __shfl_down_sync(0xffffffffu, d21, off);
        d22 += __shfl_down_sync(0xffffffffu, d22, off);
    }
    if (lane == 0) {
        float sg11 = 1.0f / (1.0f + expf(-d11));
        float sg21 = 1.0f / (1.0f + expf(-d21));
        float sg22 = 1.0f / (1.0f + expf(-d22));
        float sg12 = 1.0f / (1.0f + expf(-d12));
        g_gl[0 * NROWS + row] = -logf(sg11 + EPS_);
        g_gl[1 * NROWS + row] = -logf(1.0f - sg21 + EPS_);
        g_gl[2 * NROWS + row] = -logf(sg22 + EPS_);
        g_gl[3 * NROWS + row] = -logf(1.0f - sg12 + EPS_);
    }
}

// ---------------- final reduction (rowloss fused) ---------------------------
__global__ __launch_bounds__(1024) void finalize_kernel(float* __restrict__ out)
{
    __shared__ float red[32];
    float acc[6] = {0, 0, 0, 0, 0, 0};
    for (int i = threadIdx.x; i < NROWS; i += 1024) {
        float aas = 0, aam = 0, abs_ = 0, abm = 0;
        #pragma unroll
        for (int c = 0; c < NCHUNK; c++) {
            aas  += g_rp[c][0][i];
            aam  += g_rp[c][1][i];
            abs_ += g_rp[c][2][i];
            abm  += g_rp[c][3][i];
        }
        float cabs = 0, cabm = 0, cbbs = 0, cbbm = 0;
        for (int b = 0; b < NIB; b++) {
            cabs += g_cp[0][b][i];
            cabm += g_cp[1][b][i];
            cbbs += g_cp[2][b][i];
            cbbm += g_cp[3][b][i];
        }
        acc[0] += -logf(abm / (aas + abs_ - aam));
        acc[1] += -logf(cabm / (cbbs + cabs - cbbm));
        acc[2] += g_gl[i];
        acc[3] += g_gl[NROWS + i];
        acc[4] += g_gl[2 * NROWS + i];
        acc[5] += g_gl[3 * NROWS + i];
    }
    const int lane = threadIdx.x & 31, warp = threadIdx.x >> 5;
    float tot[6];
    for (int q = 0; q < 6; q++) {
        float v = acc[q];
        #pragma unroll
        for (int off = 16; off; off >>= 1) v += __shfl_down_sync(0xffffffffu, v, off);
        if (lane == 0) red[warp] = v;
        __syncthreads();
        if (warp == 0) {
            float w = red[lane];
            #pragma unroll
            for (int off = 16; off; off >>= 1) w += __shfl_down_sync(0xffffffffu, w, off);
            if (lane == 0) tot[q] = w;
        }
        __syncthreads();
    }
    if (threadIdx.x == 0) {
        const float inv = 1.0f / NROWS;
        float local = 0.5f * (tot[0] + tot[1]) * inv;
        float gl1   = 0.5f * (tot[2] + tot[3]) * inv;
        float gl2   = 0.5f * (tot[4] + tot[5]) * inv;
        float glob  = 0.5f * (gl1 + gl2);
        out[0] = 0.5f * local + 0.5f * glob;   // ALPHA = 0.5
    }
}

// ---------------- launch ----------------------------------------------------
extern "C" void kernel_launch(void* const* d_in, const int* in_sizes, int n_in,
                              void* d_out, int out_size)
{
    const float* z1  = (const float*)d_in[0];
    const float* z2  = (const float*)d_in[1];
    const float* lw1 = (const float*)d_in[2];
    const float* lb1 = (const float*)d_in[3];
    const float* la  = (const float*)d_in[4];
    const float* lw2 = (const float*)d_in[5];
    const float* lb2 = (const float*)d_in[6];
    const float* gw1 = (const float*)d_in[7];
    const float* gb1 = (const float*)d_in[8];
    const float* ga  = (const float*)d_in[9];
    const float* gw2 = (const float*)d_in[10];
    const float* gb2 = (const float*)d_in[11];
    const float* W   = (const float*)d_in[12];
    const int*   mask= (const int*)  d_in[13];
    float* out = (float*)d_out;

    cudaFuncSetAttribute(sim_kernel, cudaFuncAttributeMaxDynamicSharedMemorySize,
                         SIM_SMEM_BYTES);
    cudaFuncSetAttribute(gemm_hmma_kernel, cudaFuncAttributeMaxDynamicSharedMemorySize,
                         GEMM_SMEM_BYTES);

    conv_all_kernel<<<2080, 256>>>(z1, z2, lw1, lw2);

    gemm_hmma_kernel<<<dim3(32, 4, 2), 256, GEMM_SMEM_BYTES>>>(lb1, la, 1);
    gemm_hmma_kernel<<<dim3(32, 4, 2), 256, GEMM_SMEM_BYTES>>>(lb2, nullptr, 2);

    l2norm_kernel<<<dim3(NROWS, 2), 128>>>();

    sim_kernel<<<dim3(NIB, NCHUNK), 512, SIM_SMEM_BYTES>>>(mask);

    gproj_kernel<<<2, DDIM>>>(gw1, gb1, ga, gw2, gb2, W);
    sigrows_kernel<<<NROWS / 8, 256>>>(z1, z2);

    finalize_kernel<<<1, 1024>>>(out);
}

// round 14
// speedup vs baseline: 1.4595x; 1.0794x over previous
#include <cuda_runtime.h>
#include <cuda_bf16.h>
#include <cuda_fp8.h>
#include <math.h>
#include <cstdint>

#define NROWS 4096
#define DDIM  512
#define INV_TAU 5.0f
#define EXP_SCALE (INV_TAU / 256.0f)   // fp8 values scaled x16 -> dot x256
#define QSCL 16.0f
#define EPS_  1e-15f
#define L2EPS 1e-12f

#define NCHUNK 4
#define CHUNKJ (NROWS / NCHUNK)   // 1024
#define IT 128
#define NIB (NROWS / IT)          // 32

// sim kernel smem layout (bytes):
//   persistent I: AI 4 slabs @0 (4*18432), BI 4 slabs @73728
//   ring (3 stages x 18432): AJ @ +0, BJ @ +9216
//   sred after ring
#define I_BYTES   147456
#define RING_OFF  147456
#define RING_STAGE 18432
#define SRED_OFF  (RING_OFF + 3 * RING_STAGE)   // 202752
#define SIM_SMEM_BYTES (SRED_OFF + 8192)        // 210944
#define NSTAGE 64          // 16 J-tiles x 4 slabs

// gemm kernel: 3-stage ring of 32-wide bf16 k-slabs, row stride 80B
#define G_STAGE 20480
#define GEMM_SMEM_BYTES (3 * G_STAGE)

typedef unsigned long long u64;

// ---------------- scratch (static device allocations; no cudaMalloc) ------
__device__ __nv_bfloat16 g_z16a[NROWS * DDIM];
__device__ __nv_bfloat16 g_z16b[NROWS * DDIM];
__device__ __nv_bfloat16 g_T16a[NROWS * DDIM];
__device__ __nv_bfloat16 g_T16b[NROWS * DDIM];
__device__ __nv_bfloat16 g_H16a[NROWS * DDIM];
__device__ __nv_bfloat16 g_H16b[NROWS * DDIM];
__device__ __nv_bfloat16 g_w1s[DDIM * DDIM];
__device__ __nv_bfloat16 g_w2s[DDIM * DDIM];
__device__ uint8_t g_a8[NROWS * DDIM];   // fp8 e4m3, scaled x16
__device__ uint8_t g_b8[NROWS * DDIM];
__device__ float g_rowloss[2 * NROWS];
__device__ float g_gl[4 * NROWS];
__device__ float g_smp[2][16][DDIM];      // colmean partials
__device__ float g_summ[2 * DDIM];
__device__ float g_rp[NCHUNK][4][NROWS];  // row partials: aaS,aaM,abS,abM
__device__ float g_cp[4][NIB][NROWS];     // col partials: abS,abM,bbS,bbM

// ---------------- PTX helpers ----------------------------------------------
__device__ __forceinline__ uint32_t smem_u32(const void* p) {
    uint32_t a;
    asm("{ .reg .u64 tmp; cvta.to.shared.u64 tmp, %1; cvt.u32.u64 %0, tmp; }"
        : "=r"(a) : "l"(p));
    return a;
}

__device__ __forceinline__ void ldm4(uint32_t* r, uint32_t addr) {
    asm volatile("ldmatrix.sync.aligned.m8n8.x4.shared.b16 {%0,%1,%2,%3}, [%4];"
                 : "=r"(r[0]), "=r"(r[1]), "=r"(r[2]), "=r"(r[3]) : "r"(addr));
}

__device__ __forceinline__ void mma16816(float* c, const uint32_t* a,
                                         uint32_t b0, uint32_t b1) {
    asm volatile("mma.sync.aligned.m16n8k16.row.col.f32.bf16.bf16.f32 "
                 "{%0,%1,%2,%3}, {%4,%5,%6,%7}, {%8,%9}, {%0,%1,%2,%3};"
                 : "+f"(c[0]), "+f"(c[1]), "+f"(c[2]), "+f"(c[3])
                 : "r"(a[0]), "r"(a[1]), "r"(a[2]), "r"(a[3]), "r"(b0), "r"(b1));
}

__device__ __forceinline__ void mma_fp8(float* c, const uint32_t* a,
                                        uint32_t b0, uint32_t b1) {
    asm volatile("mma.sync.aligned.m16n8k32.row.col.f32.e4m3.e4m3.f32 "
                 "{%0,%1,%2,%3}, {%4,%5,%6,%7}, {%8,%9}, {%0,%1,%2,%3};"
                 : "+f"(c[0]), "+f"(c[1]), "+f"(c[2]), "+f"(c[3])
                 : "r"(a[0]), "r"(a[1]), "r"(a[2]), "r"(a[3]), "r"(b0), "r"(b1));
}

__device__ __forceinline__ void cpa16(uint32_t dst, const void* src) {
    asm volatile("cp.async.cg.shared.global [%0], [%1], 16;"
                 :: "r"(dst), "l"(src) : "memory");
}
#define CP_COMMIT() asm volatile("cp.async.commit_group;" ::: "memory")
template <int N>
__device__ __forceinline__ void cp_wait() {
    asm volatile("cp.async.wait_group %0;" :: "n"(N) : "memory");
}

// ---------------- fused fp32 -> bf16 conversion (all 4 arrays) -------------
#define Z4 (NROWS * DDIM / 4)      // 524288
#define W4 (DDIM * DDIM / 4)       // 65536
#define TOT4 (2 * Z4 + 2 * W4)

__global__ __launch_bounds__(256) void conv_all_kernel(
    const float* __restrict__ z1, const float* __restrict__ z2,
    const float* __restrict__ w1, const float* __restrict__ w2)
{
    for (int i = blockIdx.x * 256 + threadIdx.x; i < TOT4; i += gridDim.x * 256) {
        const float* src;
        __nv_bfloat16* dst;
        int o;
        if (i < Z4)            { src = z1; dst = g_z16a; o = i; }
        else if (i < 2 * Z4)   { src = z2; dst = g_z16b; o = i - Z4; }
        else if (i < 2*Z4+W4)  { src = w1; dst = g_w1s;  o = i - 2*Z4; }
        else                   { src = w2; dst = g_w2s;  o = i - 2*Z4 - W4; }
        float4 v = ((const float4*)src)[o];
        __nv_bfloat162* d = (__nv_bfloat162*)(dst + (size_t)o * 4);
        d[0] = __float22bfloat162_rn(make_float2(v.x, v.y));
        d[1] = __float22bfloat162_rn(make_float2(v.z, v.w));
    }
}

// ---------------- HMMA projector GEMM (256 threads, 3-stage ring) -----------
__global__ __launch_bounds__(256, 1) void gemm_hmma_kernel(
    const float* __restrict__ bias, const float* __restrict__ prelu_a, int stage)
{
    extern __shared__ __align__(16) char gsm[];
    const uint32_t u0 = smem_u32(gsm);

    const int t = threadIdx.x, w = t >> 5, lane = t & 31;
    const int I0 = blockIdx.x * 128, J0 = blockIdx.y * 128;
    const int z = blockIdx.z;

    const __nv_bfloat16* __restrict__ A =
        (stage == 1) ? (z ? g_z16b : g_z16a) : (z ? g_T16b : g_T16a);
    const __nv_bfloat16* __restrict__ Wm = (stage == 1) ? g_w1s : g_w2s;

    const int lr16 = lane & 15, lh = lane >> 4;
    const uint32_t aoff = (w * 16 + lr16) * 80 + lh * 16;
    uint32_t boff[8];
    #pragma unroll
    for (int p = 0; p < 8; p++)
        boff[p] = (p * 16 + lr16) * 80 + lh * 16;

    int rr[2], cc8[2];
    uint32_t dd[2];
    #pragma unroll
    for (int q = 0; q < 2; q++) {
        int id = t + q * 256;
        rr[q] = id >> 2; cc8[q] = (id & 3) * 8;
        dd[q] = rr[q] * 80 + (id & 3) * 16;
    }

    float acc[8][2][4];
    #pragma unroll
    for (int p = 0; p < 8; p++)
        #pragma unroll
        for (int h = 0; h < 2; h++)
            #pragma unroll
            for (int q = 0; q < 4; q++) acc[p][h][q] = 0.0f;

    #pragma unroll
    for (int s = 0; s < 2; s++) {
        const uint32_t b = u0 + s * G_STAGE;
        const int kb = s * 32;
        #pragma unroll
        for (int q = 0; q < 2; q++) {
            cpa16(b + dd[q], A + (size_t)(I0 + rr[q]) * DDIM + kb + cc8[q]);
            cpa16(b + 10240 + dd[q], Wm + (size_t)(J0 + rr[q]) * DDIM + kb + cc8[q]);
        }
        CP_COMMIT();
    }

    for (int ck = 0; ck < 16; ck++) {
        cp_wait<1>();
        __syncthreads();
        if (ck + 2 < 16) {
            const uint32_t b = u0 + ((ck + 2) % 3) * G_STAGE;
            const int kb = (ck + 2) * 32;
            #pragma unroll
            for (int q = 0; q < 2; q++) {
                cpa16(b + dd[q], A + (size_t)(I0 + rr[q]) * DDIM + kb + cc8[q]);
                cpa16(b + 10240 + dd[q], Wm + (size_t)(J0 + rr[q]) * DDIM + kb + cc8[q]);
            }
        }
        CP_COMMIT();
        const uint32_t uA = u0 + (ck % 3) * G_STAGE;
        const uint32_t uW = uA + 10240;
        #pragma unroll
        for (int ks = 0; ks < 2; ks++) {
            uint32_t fA[4];
            ldm4(fA, uA + aoff + ks * 32);
            #pragma unroll
            for (int p = 0; p < 8; p++) {
                uint32_t fW[4];
                ldm4(fW, uW + boff[p] + ks * 32);
                mma16816(acc[p][0], fA, fW[0], fW[2]);
                mma16816(acc[p][1], fA, fW[1], fW[3]);
            }
        }
    }

    const int er = lane >> 2, ec = 2 * (lane & 3);
    const int row = I0 + w * 16 + er;
    const bool do_prelu = (prelu_a != nullptr);
    const float pa = do_prelu ? prelu_a[0] : 0.0f;

    __nv_bfloat16* Out = (stage == 1) ? (z ? g_T16b : g_T16a)
                                      : (z ? g_H16b : g_H16a);
    #pragma unroll
    for (int p = 0; p < 8; p++) {
        #pragma unroll
        for (int h = 0; h < 2; h++) {
            int col = J0 + p * 16 + h * 8 + ec;
            float b0 = bias[col], b1 = bias[col + 1];
            float v0 = acc[p][h][0] + b0, v1 = acc[p][h][1] + b1;
            float v2 = acc[p][h][2] + b0, v3 = acc[p][h][3] + b1;
            if (do_prelu) {
                v0 = (v0 >= 0.0f) ? v0 : pa * v0;
                v1 = (v1 >= 0.0f) ? v1 : pa * v1;
                v2 = (v2 >= 0.0f) ? v2 : pa * v2;
                v3 = (v3 >= 0.0f) ? v3 : pa * v3;
            }
            *(__nv_bfloat162*)(Out + (size_t)row * DDIM + col) =
                __float22bfloat162_rn(make_float2(v0, v1));
            *(__nv_bfloat162*)(Out + (size_t)(row + 8) * DDIM + col) =
                __float22bfloat162_rn(make_float2(v2, v3));
        }
    }
}

// ---------------- row L2 normalization (bf16 in -> fp8 e4m3 out, x16) ------
__global__ __launch_bounds__(128) void l2norm_kernel()
{
    const __nv_bfloat16* h = blockIdx.y ? g_H16b : g_H16a;
    uint8_t* o8 = blockIdx.y ? g_b8 : g_a8;
    const int row = blockIdx.x;
    const int t = threadIdx.x;
    const __nv_bfloat162* src = (const __nv_bfloat162*)&h[(size_t)row * DDIM + t*4];
    __nv_bfloat162 h0 = src[0], h1 = src[1];
    float2 f0 = __bfloat1622float2(h0), f1 = __bfloat1622float2(h1);
    float ss = f0.x*f0.x + f0.y*f0.y + f1.x*f1.x + f1.y*f1.y;
    #pragma unroll
    for (int off = 16; off; off >>= 1) ss += __shfl_down_sync(0xffffffffu, ss, off);
    __shared__ float sm[4];
    __shared__ float stot;
    if ((t & 31) == 0) sm[t >> 5] = ss;
    __syncthreads();
    if (t == 0) stot = sm[0] + sm[1] + sm[2] + sm[3];
    __syncthreads();
    float scale = QSCL / fmaxf(sqrtf(stot), L2EPS);
    __nv_fp8x2_storage_t lo = __nv_cvt_float2_to_fp8x2(
        make_float2(f0.x * scale, f0.y * scale), __NV_SATFINITE, __NV_E4M3);
    __nv_fp8x2_storage_t hi = __nv_cvt_float2_to_fp8x2(
        make_float2(f1.x * scale, f1.y * scale), __NV_SATFINITE, __NV_E4M3);
    uint32_t packed = (uint32_t)lo | ((uint32_t)hi << 16);
    *(uint32_t*)(o8 + (size_t)row * DDIM + t * 4) = packed;
}

// ---------------- FP8 similarity kernel (512 thr, persistent I tiles) -------
// CTA (Ib, c): I-rows Ib*128..+127 resident in smem; 16 J-tiles of 64, 4 slabs.
// Warp w: rows (w&7)*16..+15, column half (w>>3)*32..+31 of each J-tile.
__global__ __launch_bounds__(512, 1) void sim_kernel(const int* __restrict__ mask)
{
    extern __shared__ __align__(16) char dsm[];
    const uint32_t u0 = smem_u32(dsm);
    const uint32_t uRing = u0 + RING_OFF;
    float* sred = (float*)(dsm + SRED_OFF);   // 2048 floats

    const int t = threadIdx.x, w = t >> 5, lane = t & 31;
    const int rw = w & 7, ch = w >> 3;
    const int Ib = blockIdx.x, c = blockIdx.y;
    const int I = Ib * IT;
    const int Jbase = c * CHUNKJ;

    const int lr16 = lane & 15, lh = lane >> 4;
    const uint32_t aoff = (rw * 16 + lr16) * 144 + lh * 16;
    uint32_t boff[2];
    #pragma unroll
    for (int p = 0; p < 2; p++)
        boff[p] = ((ch * 2 + p) * 16 + lr16) * 144 + lh * 16;

    const int er = lane >> 2;
    const int ec = 2 * (lane & 3);
    const size_t gr0 = (size_t)(I + rw * 16 + er);

    // J-tile cp.async mapping: AJ/BJ each 512 chunks -> 1/thread
    const int rJ = t >> 3;
    const int cJ = (t & 7) * 16;
    const uint32_t dJ = rJ * 144 + cJ;

    float rs_aa0 = 0, rs_aa1 = 0, rm_aa0 = 0, rm_aa1 = 0;
    float rs_ab0 = 0, rs_ab1 = 0, rm_ab0 = 0, rm_ab1 = 0;

    float acc[3][4][4];
    #pragma unroll
    for (int m = 0; m < 3; m++)
        #pragma unroll
        for (int nb = 0; nb < 4; nb++)
            #pragma unroll
            for (int q = 0; q < 4; q++) acc[m][nb][q] = 0.0f;

    // ---- prologue: persistent I tiles (AI @0, BI @73728), 4 slabs each ----
    #pragma unroll
    for (int q = 0; q < 8; q++) {
        int id = t + q * 512;            // 0..4095
        int slab = id >> 10;             // 0..3
        int rem = id & 1023;
        int row = rem >> 3, c16 = (rem & 7) * 16;
        uint32_t dst = u0 + slab * 18432 + row * 144 + c16;
        const size_t gsrc = (size_t)(I + row) * DDIM + slab * 128 + c16;
        cpa16(dst, g_a8 + gsrc);
        cpa16(dst + 73728, g_b8 + gsrc);
    }
    CP_COMMIT();

    #define SIM_ISSUE(sidx)                                                     \
    do {                                                                        \
        const int _s = (sidx);                                                  \
        const uint32_t _b = uRing + (_s % 3) * RING_STAGE;                      \
        const int _J0 = Jbase + (_s >> 2) * 64;                                 \
        const int _kb = (_s & 3) * 128;                                         \
        const size_t _g = (size_t)(_J0 + rJ) * DDIM + _kb + cJ;                 \
        cpa16(_b + dJ, g_a8 + _g);                                              \
        cpa16(_b + 9216 + dJ, g_b8 + _g);                                       \
    } while (0)

    SIM_ISSUE(0); CP_COMMIT();
    SIM_ISSUE(1); CP_COMMIT();

    for (int s = 0; s < NSTAGE; s++) {
        cp_wait<1>();
        __syncthreads();
        if (s + 2 < NSTAGE) SIM_ISSUE(s + 2);
        CP_COMMIT();

        const uint32_t uAI = u0 + (s & 3) * 18432;
        const uint32_t uBI = uAI + 73728;
        const uint32_t uAJ = uRing + (s % 3) * RING_STAGE;
        const uint32_t uBJ = uAJ + 9216;
        #pragma unroll
        for (int ks = 0; ks < 4; ks++) {      // each ks = 32 fp8 k-elements
            uint32_t fA[4], fB[4], fJA[2][4], fJB[2][4];
            ldm4(fA, uAI + aoff + ks * 32);
            ldm4(fB, uBI + aoff + ks * 32);
            #pragma unroll
            for (int p = 0; p < 2; p++) {
                ldm4(fJA[p], uAJ + boff[p] + ks * 32);
                ldm4(fJB[p], uBJ + boff[p] + ks * 32);
            }
            #pragma unroll
            for (int p = 0; p < 2; p++) {
                mma_fp8(acc[0][2*p],   fA, fJA[p][0], fJA[p][2]);
                mma_fp8(acc[0][2*p+1], fA, fJA[p][1], fJA[p][3]);
                mma_fp8(acc[1][2*p],   fA, fJB[p][0], fJB[p][2]);
                mma_fp8(acc[1][2*p+1], fA, fJB[p][1], fJB[p][3]);
                mma_fp8(acc[2][2*p],   fB, fJB[p][0], fJB[p][2]);
                mma_fp8(acc[2][2*p+1], fB, fJB[p][1], fJB[p][3]);
            }
        }

        if ((s & 3) == 3) {
            const int J0 = Jbase + (s >> 2) * 64;
            #pragma unroll
            for (int nb = 0; nb < 4; nb++) {
                const int gc = J0 + (ch * 4 + nb) * 8 + ec;
                int2 m0 = *(const int2*)(mask + gr0 * NROWS + gc);
                int2 m1 = *(const int2*)(mask + (gr0 + 8) * NROWS + gc);
                float m00 = (float)m0.x, m01 = (float)m0.y;
                float m10 = (float)m1.x, m11 = (float)m1.y;

                float ea0 = __expf(acc[0][nb][0] * EXP_SCALE);
                float ea1 = __expf(acc[0][nb][1] * EXP_SCALE);
                float ea2 = __expf(acc[0][nb][2] * EXP_SCALE);
                float ea3 = __expf(acc[0][nb][3] * EXP_SCALE);
                float eb0 = __expf(acc[1][nb][0] * EXP_SCALE);
                float eb1 = __expf(acc[1][nb][1] * EXP_SCALE);
                float eb2 = __expf(acc[1][nb][2] * EXP_SCALE);
                float eb3 = __expf(acc[1][nb][3] * EXP_SCALE);
                float ec0 = __expf(acc[2][nb][0] * EXP_SCALE);
                float ec1 = __expf(acc[2][nb][1] * EXP_SCALE);
                float ec2 = __expf(acc[2][nb][2] * EXP_SCALE);
                float ec3 = __expf(acc[2][nb][3] * EXP_SCALE);

                rs_aa0 += ea0 + ea1;  rm_aa0 += ea0 * m00 + ea1 * m01;
                rs_aa1 += ea2 + ea3;  rm_aa1 += ea2 * m10 + ea3 * m11;
                rs_ab0 += eb0 + eb1;  rm_ab0 += eb0 * m00 + eb1 * m01;
                rs_ab1 += eb2 + eb3;  rm_ab1 += eb2 * m10 + eb3 * m11;

                float v[8];
                v[0] = eb0 + eb2;              v[1] = eb1 + eb3;
                v[2] = eb0 * m00 + eb2 * m10;  v[3] = eb1 * m01 + eb3 * m11;
                v[4] = ec0 + ec2;              v[5] = ec1 + ec3;
                v[6] = ec0 * m00 + ec2 * m10;  v[7] = ec1 * m01 + ec3 * m11;
                #pragma unroll
                for (int q = 0; q < 8; q++) {
                    v[q] += __shfl_down_sync(0xffffffffu, v[q], 16);
                    v[q] += __shfl_down_sync(0xffffffffu, v[q], 8);
                    v[q] += __shfl_down_sync(0xffffffffu, v[q], 4);
                }
                if (lane < 4) {
                    int cl = nb * 8 + 2 * lane;
                    sred[w * 128 + 0 * 32 + cl]     = v[0];
                    sred[w * 128 + 0 * 32 + cl + 1] = v[1];
                    sred[w * 128 + 1 * 32 + cl]     = v[2];
                    sred[w * 128 + 1 * 32 + cl + 1] = v[3];
                    sred[w * 128 + 2 * 32 + cl]     = v[4];
                    sred[w * 128 + 2 * 32 + cl + 1] = v[5];
                    sred[w * 128 + 3 * 32 + cl]     = v[6];
                    sred[w * 128 + 3 * 32 + cl + 1] = v[7];
                }
            }
            __syncthreads();
            if (t < 256) {
                int q = t >> 6, colg = t & 63;
                int ch2 = colg >> 5, cl = colg & 31;
                float sacc = 0.0f;
                #pragma unroll
                for (int r2 = 0; r2 < 8; r2++)
                    sacc += sred[(ch2 * 8 + r2) * 128 + q * 32 + cl];
                g_cp[q][Ib][J0 + colg] = sacc;
            }
            #pragma unroll
            for (int m = 0; m < 3; m++)
                #pragma unroll
                for (int nb = 0; nb < 4; nb++)
                    #pragma unroll
                    for (int q = 0; q < 4; q++) acc[m][nb][q] = 0.0f;
        }
    }

    #pragma unroll
    for (int d = 1; d < 4; d <<= 1) {
        rs_aa0 += __shfl_down_sync(0xffffffffu, rs_aa0, d, 4);
        rs_aa1 += __shfl_down_sync(0xffffffffu, rs_aa1, d, 4);
        rm_aa0 += __shfl_down_sync(0xffffffffu, rm_aa0, d, 4);
        rm_aa1 += __shfl_down_sync(0xffffffffu, rm_aa1, d, 4);
        rs_ab0 += __shfl_down_sync(0xffffffffu, rs_ab0, d, 4);
        rs_ab1 += __shfl_down_sync(0xffffffffu, rs_ab1, d, 4);
        rm_ab0 += __shfl_down_sync(0xffffffffu, rm_ab0, d, 4);
        rm_ab1 += __shfl_down_sync(0xffffffffu, rm_ab1, d, 4);
    }
    __syncthreads();
    const int r0 = rw * 16 + er;
    if (ch == 1 && (lane & 3) == 0) {
        sred[r0 * 4 + 0] = rs_aa0;  sred[r0 * 4 + 1] = rm_aa0;
        sred[r0 * 4 + 2] = rs_ab0;  sred[r0 * 4 + 3] = rm_ab0;
        sred[(r0 + 8) * 4 + 0] = rs_aa1;  sred[(r0 + 8) * 4 + 1] = rm_aa1;
        sred[(r0 + 8) * 4 + 2] = rs_ab1;  sred[(r0 + 8) * 4 + 3] = rm_ab1;
    }
    __syncthreads();
    if (ch == 0 && (lane & 3) == 0) {
        g_rp[c][0][I + r0]     = rs_aa0 + sred[r0 * 4 + 0];
        g_rp[c][1][I + r0]     = rm_aa0 + sred[r0 * 4 + 1];
        g_rp[c][2][I + r0]     = rs_ab0 + sred[r0 * 4 + 2];
        g_rp[c][3][I + r0]     = rm_ab0 + sred[r0 * 4 + 3];
        g_rp[c][0][I + r0 + 8] = rs_aa1 + sred[(r0 + 8) * 4 + 0];
        g_rp[c][1][I + r0 + 8] = rm_aa1 + sred[(r0 + 8) * 4 + 1];
        g_rp[c][2][I + r0 + 8] = rs_ab1 + sred[(r0 + 8) * 4 + 2];
        g_rp[c][3][I + r0 + 8] = rm_ab1 + sred[(r0 + 8) * 4 + 3];
    }
}

// ---------------- combine partials -> per-row losses ------------------------
__global__ __launch_bounds__(256) void rowloss2_kernel()
{
    int i = blockIdx.x * 256 + threadIdx.x;
    float aas = 0, aam = 0, abs_ = 0, abm = 0;
    #pragma unroll
    for (int c = 0; c < NCHUNK; c++) {
        aas  += g_rp[c][0][i];
        aam  += g_rp[c][1][i];
        abs_ += g_rp[c][2][i];
        abm  += g_rp[c][3][i];
    }
    float cabs = 0, cabm = 0, cbbs = 0, cbbm = 0;
    for (int b = 0; b < NIB; b++) {
        cabs += g_cp[0][b][i];
        cabm += g_cp[1][b][i];
        cbbs += g_cp[2][b][i];
        cbbm += g_cp[3][b][i];
    }
    g_rowloss[i]         = -logf(abm / (aas + abs_ - aam));
    g_rowloss[NROWS + i] = -logf(cabm / (cbbs + cabs - cbbm));
}

// ---------------- column-mean partials (readout s) --------------------------
__global__ __launch_bounds__(512) void colmean_kernel(const float* __restrict__ z1,
                                                      const float* __restrict__ z2)
{
    const float* z = blockIdx.y ? z2 : z1;
    const int rb = blockIdx.x;   // 16 row blocks of 256
    const int t = threadIdx.x;
    float a0 = 0, a1 = 0, a2 = 0, a3 = 0;
    const int r0 = rb * 256;
    for (int r = r0; r < r0 + 256; r += 4) {
        a0 += z[(size_t)(r+0) * DDIM + t];
        a1 += z[(size_t)(r+1) * DDIM + t];
        a2 += z[(size_t)(r+2) * DDIM + t];
        a3 += z[(size_t)(r+3) * DDIM + t];
    }
    g_smp[blockIdx.y][rb][t] = (a0 + a1 + a2 + a3) * (1.0f / NROWS);
}

// ---------------- global projector chain: summ_p = W @ proj(s_p) -----------
__device__ __forceinline__ void mv_stage(const float* __restrict__ Wm,
                                         const float* __restrict__ bias,
                                         const float* vin, float* vout,
                                         float pa, bool prelu_on,
                                         int warp, int lane)
{
    for (int rr = 0; rr < 32; rr++) {
        int o = warp * 32 + rr;
        const float* wr = Wm + (size_t)o * DDIM;
        float acc = 0.0f;
        for (int i = lane; i < DDIM; i += 32) acc += wr[i] * vin[i];
        #pragma unroll
        for (int off = 16; off; off >>= 1) acc += __shfl_down_sync(0xffffffffu, acc, off);
        if (lane == 0) {
            float v = acc + (bias ? bias[o] : 0.0f);
            if (prelu_on) v = (v >= 0.0f) ? v : pa * v;
            vout[o] = v;
        }
    }
}

__global__ __launch_bounds__(512) void gproj_kernel(
    const float* __restrict__ gw1, const float* __restrict__ gb1,
    const float* __restrict__ ga,  const float* __restrict__ gw2,
    const float* __restrict__ gb2, const float* __restrict__ W)
{
    __shared__ float v[DDIM], u[DDIM], hh[DDIM];
    const int p = blockIdx.x;
    const int t = threadIdx.x, warp = t >> 5, lane = t & 31;
    float sv = 0.0f;
    #pragma unroll
    for (int rb = 0; rb < 16; rb++) sv += g_smp[p][rb][t];
    v[t] = sv;
    __syncthreads();
    mv_stage(gw1, gb1, v, u, ga[0], true, warp, lane);
    __syncthreads();
    mv_stage(gw2, gb2, u, hh, 0.0f, false, warp, lane);
    __syncthreads();
    for (int rr = 0; rr < 32; rr++) {
        int o = warp * 32 + rr;
        const float* wr = W + (size_t)o * DDIM;
        float acc = 0.0f;
        for (int i = lane; i < DDIM; i += 32) acc += wr[i] * hh[i];
        #pragma unroll
        for (int off = 16; off; off >>= 1) acc += __shfl_down_sync(0xffffffffu, acc, off);
        if (lane == 0) g_summ[p * DDIM + o] = acc;
    }
}

// ---------------- per-row discriminator terms ------------------------------
__global__ __launch_bounds__(256) void sigrows_kernel(const float* __restrict__ z1,
                                                      const float* __restrict__ z2)
{
    const int warp = threadIdx.x >> 5, lane = threadIdx.x & 31;
    const int row = blockIdx.x * 8 + warp;
    const float* r1 = z1 + (size_t)row * DDIM;
    const float* r2 = z2 + (size_t)row * DDIM;
    float d11 = 0, d12 = 0, d21 = 0, d22 = 0;
    for (int i = lane; i < DDIM; i += 32) {
        float a = r1[i], b = r2[i];
        float s1 = g_summ[i], s2 = g_summ[DDIM + i];
        d11 += a * s1; d12 += a * s2; d21 += b * s1; d22 += b * s2;
    }
    #pragma unroll
    for (int off = 16; off; off >>= 1) {
        d11 += __shfl_down_sync(0xffffffffu, d11, off);
        d12 += __shfl_down_sync(0xffffffffu, d12, off);
        d21 += __shfl_down_sync(0xffffffffu, d21, off);
        d22 += __shfl_down_sync(0xffffffffu, d22, off);
    }
    if (lane == 0) {
        float sg11 = 1.0f / (1.0f + expf(-d11));
        float sg21 = 1.0f / (1.0f + expf(-d21));
        float sg22 = 1.0f / (1.0f + expf(-d22));
        float sg12 = 1.0f / (1.0f + expf(-d12));
        g_gl[0 * NROWS + row] = -logf(sg11 + EPS_);
        g_gl[1 * NROWS + row] = -logf(1.0f - sg21 + EPS_);
        g_gl[2 * NROWS + row] = -logf(sg22 + EPS_);
        g_gl[3 * NROWS + row] = -logf(1.0f - sg12 + EPS_);
    }
}

// ---------------- final deterministic reduction ----------------------------
__global__ __launch_bounds__(1024) void finalize_kernel(float* __restrict__ out)
{
    __shared__ float red[32];
    float acc[6] = {0, 0, 0, 0, 0, 0};
    for (int i = threadIdx.x; i < NROWS; i += 1024) {
        acc[0] += g_rowloss[i];
        acc[1] += g_rowloss[NROWS + i];
        acc[2] += g_gl[i];
        acc[3] += g_gl[NROWS + i];
        acc[4] += g_gl[2 * NROWS + i];
        acc[5] += g_gl[3 * NROWS + i];
    }
    const int lane = threadIdx.x & 31, warp = threadIdx.x >> 5;
    float tot[6];
    for (int q = 0; q < 6; q++) {
        float v = acc[q];
        #pragma unroll
        for (int off = 16; off; off >>= 1) v += __shfl_down_sync(0xffffffffu, v, off);
        if (lane == 0) red[warp] = v;
        __syncthreads();
        if (warp == 0) {
            float w = red[lane];
            #pragma unroll
            for (int off = 16; off; off >>= 1) w += __shfl_down_sync(0xffffffffu, w, off);
            if (lane == 0) tot[q] = w;
        }
        __syncthreads();
    }
    if (threadIdx.x == 0) {
        const float inv = 1.0f / NROWS;
        float local = 0.5f * (tot[0] + tot[1]) * inv;
        float gl1   = 0.5f * (tot[2] + tot[3]) * inv;
        float gl2   = 0.5f * (tot[4] + tot[5]) * inv;
        float glob  = 0.5f * (gl1 + gl2);
        out[0] = 0.5f * local + 0.5f * glob;   // ALPHA = 0.5
    }
}

// ---------------- launch ----------------------------------------------------
extern "C" void kernel_launch(void* const* d_in, const int* in_sizes, int n_in,
                              void* d_out, int out_size)
{
    const float* z1  = (const float*)d_in[0];
    const float* z2  = (const float*)d_in[1];
    const float* lw1 = (const float*)d_in[2];
    const float* lb1 = (const float*)d_in[3];
    const float* la  = (const float*)d_in[4];
    const float* lw2 = (const float*)d_in[5];
    const float* lb2 = (const float*)d_in[6];
    const float* gw1 = (const float*)d_in[7];
    const float* gb1 = (const float*)d_in[8];
    const float* ga  = (const float*)d_in[9];
    const float* gw2 = (const float*)d_in[10];
    const float* gb2 = (const float*)d_in[11];
    const float* W   = (const float*)d_in[12];
    const int*   mask= (const int*)  d_in[13];
    float* out = (float*)d_out;

    cudaFuncSetAttribute(sim_kernel, cudaFuncAttributeMaxDynamicSharedMemorySize,
                         SIM_SMEM_BYTES);
    cudaFuncSetAttribute(gemm_hmma_kernel, cudaFuncAttributeMaxDynamicSharedMemorySize,
                         GEMM_SMEM_BYTES);

    conv_all_kernel<<<2048, 256>>>(z1, z2, lw1, lw2);

    gemm_hmma_kernel<<<dim3(32, 4, 2), 256, GEMM_SMEM_BYTES>>>(lb1, la, 1);
    gemm_hmma_kernel<<<dim3(32, 4, 2), 256, GEMM_SMEM_BYTES>>>(lb2, nullptr, 2);

    l2norm_kernel<<<dim3(NROWS, 2), 128>>>();

    sim_kernel<<<dim3(NIB, NCHUNK), 512, SIM_SMEM_BYTES>>>(mask);
    rowloss2_kernel<<<NROWS / 256, 256>>>();

    colmean_kernel<<<dim3(16, 2), 512>>>(z1, z2);
    gproj_kernel<<<2, DDIM>>>(gw1, gb1, ga, gw2, gb2, W);
    sigrows_kernel<<<NROWS / 8, 256>>>(z1, z2);

    finalize_kernel<<<1, 1024>>>(out);
}

// round 15
// speedup vs baseline: 1.4701x; 1.0073x over previous
#include <cuda_runtime.h>
#include <cuda_bf16.h>
#include <cuda_fp8.h>
#include <math.h>
#include <cstdint>

#define NROWS 4096
#define DDIM  512
#define INV_TAU 5.0f
#define EXP_SCALE (INV_TAU / 256.0f)   // fp8 values scaled x16 -> dot x256
#define QSCL 16.0f
#define EPS_  1e-15f
#define L2EPS 1e-12f

#define NCHUNK 4
#define CHUNKJ (NROWS / NCHUNK)   // 1024
#define IT 128
#define NIB (NROWS / IT)          // 32

// sim kernel smem layout (bytes):
//   persistent I: AI 4 slabs @0 (4*18432), BI 4 slabs @73728
//   ring (3 stages x 18432): AJ @ +0, BJ @ +9216
//   sred after ring
#define I_BYTES   147456
#define RING_OFF  147456
#define RING_STAGE 18432
#define SRED_OFF  (RING_OFF + 3 * RING_STAGE)   // 202752
#define SIM_SMEM_BYTES (SRED_OFF + 8192)        // 210944
#define NSTAGE 64          // 16 J-tiles x 4 slabs

// gemm kernel: 3-stage ring of 32-wide bf16 k-slabs, row stride 80B
#define G_STAGE 20480
#define GEMM_SMEM_BYTES (3 * G_STAGE)

typedef unsigned long long u64;

// ---------------- scratch (static device allocations; no cudaMalloc) ------
__device__ __nv_bfloat16 g_z16a[NROWS * DDIM];
__device__ __nv_bfloat16 g_z16b[NROWS * DDIM];
__device__ __nv_bfloat16 g_T16a[NROWS * DDIM];
__device__ __nv_bfloat16 g_T16b[NROWS * DDIM];
__device__ __nv_bfloat16 g_H16a[NROWS * DDIM];
__device__ __nv_bfloat16 g_H16b[NROWS * DDIM];
__device__ __nv_bfloat16 g_w1s[DDIM * DDIM];
__device__ __nv_bfloat16 g_w2s[DDIM * DDIM];
__device__ uint8_t g_a8[NROWS * DDIM];   // fp8 e4m3, scaled x16
__device__ uint8_t g_b8[NROWS * DDIM];
__device__ float g_rowloss[2 * NROWS];
__device__ float g_gl[4 * NROWS];
__device__ float g_smp[2][16][DDIM];      // colmean partials
__device__ float g_summ[2 * DDIM];
__device__ float g_rp[NCHUNK][4][NROWS];  // row partials: aaS,aaM,abS,abM
__device__ float g_cp[4][NIB][NROWS];     // col partials: abS,abM,bbS,bbM

// ---------------- PTX helpers ----------------------------------------------
__device__ __forceinline__ uint32_t smem_u32(const void* p) {
    uint32_t a;
    asm("{ .reg .u64 tmp; cvta.to.shared.u64 tmp, %1; cvt.u32.u64 %0, tmp; }"
        : "=r"(a) : "l"(p));
    return a;
}

__device__ __forceinline__ void ldm4(uint32_t* r, uint32_t addr) {
    asm volatile("ldmatrix.sync.aligned.m8n8.x4.shared.b16 {%0,%1,%2,%3}, [%4];"
                 : "=r"(r[0]), "=r"(r[1]), "=r"(r[2]), "=r"(r[3]) : "r"(addr));
}

__device__ __forceinline__ void mma16816(float* c, const uint32_t* a,
                                         uint32_t b0, uint32_t b1) {
    asm volatile("mma.sync.aligned.m16n8k16.row.col.f32.bf16.bf16.f32 "
                 "{%0,%1,%2,%3}, {%4,%5,%6,%7}, {%8,%9}, {%0,%1,%2,%3};"
                 : "+f"(c[0]), "+f"(c[1]), "+f"(c[2]), "+f"(c[3])
                 : "r"(a[0]), "r"(a[1]), "r"(a[2]), "r"(a[3]), "r"(b0), "r"(b1));
}

__device__ __forceinline__ void mma_fp8(float* c, const uint32_t* a,
                                        uint32_t b0, uint32_t b1) {
    asm volatile("mma.sync.aligned.m16n8k32.row.col.f32.e4m3.e4m3.f32 "
                 "{%0,%1,%2,%3}, {%4,%5,%6,%7}, {%8,%9}, {%0,%1,%2,%3};"
                 : "+f"(c[0]), "+f"(c[1]), "+f"(c[2]), "+f"(c[3])
                 : "r"(a[0]), "r"(a[1]), "r"(a[2]), "r"(a[3]), "r"(b0), "r"(b1));
}

__device__ __forceinline__ void cpa16(uint32_t dst, const void* src) {
    asm volatile("cp.async.cg.shared.global [%0], [%1], 16;"
                 :: "r"(dst), "l"(src) : "memory");
}
#define CP_COMMIT() asm volatile("cp.async.commit_group;" ::: "memory")
template <int N>
__device__ __forceinline__ void cp_wait() {
    asm volatile("cp.async.wait_group %0;" :: "n"(N) : "memory");
}

// ---------------- fused fp32 -> bf16 conversion (all 4 arrays) -------------
#define Z4 (NROWS * DDIM / 4)      // 524288
#define W4 (DDIM * DDIM / 4)       // 65536
#define TOT4 (2 * Z4 + 2 * W4)

__global__ __launch_bounds__(256) void conv_all_kernel(
    const float* __restrict__ z1, const float* __restrict__ z2,
    const float* __restrict__ w1, const float* __restrict__ w2)
{
    for (int i = blockIdx.x * 256 + threadIdx.x; i < TOT4; i += gridDim.x * 256) {
        const float* src;
        __nv_bfloat16* dst;
        int o;
        if (i < Z4)            { src = z1; dst = g_z16a; o = i; }
        else if (i < 2 * Z4)   { src = z2; dst = g_z16b; o = i - Z4; }
        else if (i < 2*Z4+W4)  { src = w1; dst = g_w1s;  o = i - 2*Z4; }
        else                   { src = w2; dst = g_w2s;  o = i - 2*Z4 - W4; }
        float4 v = ((const float4*)src)[o];
        __nv_bfloat162* d = (__nv_bfloat162*)(dst + (size_t)o * 4);
        d[0] = __float22bfloat162_rn(make_float2(v.x, v.y));
        d[1] = __float22bfloat162_rn(make_float2(v.z, v.w));
    }
}

// ---------------- HMMA projector GEMM (256 threads, 3-stage ring, 2 CTA/SM) -
__global__ __launch_bounds__(256, 2) void gemm_hmma_kernel(
    const float* __restrict__ bias, const float* __restrict__ prelu_a, int stage)
{
    extern __shared__ __align__(16) char gsm[];
    const uint32_t u0 = smem_u32(gsm);

    const int t = threadIdx.x, w = t >> 5, lane = t & 31;
    const int I0 = blockIdx.x * 128, J0 = blockIdx.y * 128;
    const int z = blockIdx.z;

    const __nv_bfloat16* __restrict__ A =
        (stage == 1) ? (z ? g_z16b : g_z16a) : (z ? g_T16b : g_T16a);
    const __nv_bfloat16* __restrict__ Wm = (stage == 1) ? g_w1s : g_w2s;

    const int lr16 = lane & 15, lh = lane >> 4;
    const uint32_t aoff = (w * 16 + lr16) * 80 + lh * 16;
    uint32_t boff[8];
    #pragma unroll
    for (int p = 0; p < 8; p++)
        boff[p] = (p * 16 + lr16) * 80 + lh * 16;

    int rr[2], cc8[2];
    uint32_t dd[2];
    #pragma unroll
    for (int q = 0; q < 2; q++) {
        int id = t + q * 256;
        rr[q] = id >> 2; cc8[q] = (id & 3) * 8;
        dd[q] = rr[q] * 80 + (id & 3) * 16;
    }

    float acc[8][2][4];
    #pragma unroll
    for (int p = 0; p < 8; p++)
        #pragma unroll
        for (int h = 0; h < 2; h++)
            #pragma unroll
            for (int q = 0; q < 4; q++) acc[p][h][q] = 0.0f;

    #pragma unroll
    for (int s = 0; s < 2; s++) {
        const uint32_t b = u0 + s * G_STAGE;
        const int kb = s * 32;
        #pragma unroll
        for (int q = 0; q < 2; q++) {
            cpa16(b + dd[q], A + (size_t)(I0 + rr[q]) * DDIM + kb + cc8[q]);
            cpa16(b + 10240 + dd[q], Wm + (size_t)(J0 + rr[q]) * DDIM + kb + cc8[q]);
        }
        CP_COMMIT();
    }

    for (int ck = 0; ck < 16; ck++) {
        cp_wait<1>();
        __syncthreads();
        if (ck + 2 < 16) {
            const uint32_t b = u0 + ((ck + 2) % 3) * G_STAGE;
            const int kb = (ck + 2) * 32;
            #pragma unroll
            for (int q = 0; q < 2; q++) {
                cpa16(b + dd[q], A + (size_t)(I0 + rr[q]) * DDIM + kb + cc8[q]);
                cpa16(b + 10240 + dd[q], Wm + (size_t)(J0 + rr[q]) * DDIM + kb + cc8[q]);
            }
        }
        CP_COMMIT();
        const uint32_t uA = u0 + (ck % 3) * G_STAGE;
        const uint32_t uW = uA + 10240;
        #pragma unroll
        for (int ks = 0; ks < 2; ks++) {
            uint32_t fA[4];
            ldm4(fA, uA + aoff + ks * 32);
            #pragma unroll
            for (int p = 0; p < 8; p++) {
                uint32_t fW[4];
                ldm4(fW, uW + boff[p] + ks * 32);
                mma16816(acc[p][0], fA, fW[0], fW[2]);
                mma16816(acc[p][1], fA, fW[1], fW[3]);
            }
        }
    }

    const int er = lane >> 2, ec = 2 * (lane & 3);
    const int row = I0 + w * 16 + er;
    const bool do_prelu = (prelu_a != nullptr);
    const float pa = do_prelu ? prelu_a[0] : 0.0f;

    __nv_bfloat16* Out = (stage == 1) ? (z ? g_T16b : g_T16a)
                                      : (z ? g_H16b : g_H16a);
    #pragma unroll
    for (int p = 0; p < 8; p++) {
        #pragma unroll
        for (int h = 0; h < 2; h++) {
            int col = J0 + p * 16 + h * 8 + ec;
            float b0 = bias[col], b1 = bias[col + 1];
            float v0 = acc[p][h][0] + b0, v1 = acc[p][h][1] + b1;
            float v2 = acc[p][h][2] + b0, v3 = acc[p][h][3] + b1;
            if (do_prelu) {
                v0 = (v0 >= 0.0f) ? v0 : pa * v0;
                v1 = (v1 >= 0.0f) ? v1 : pa * v1;
                v2 = (v2 >= 0.0f) ? v2 : pa * v2;
                v3 = (v3 >= 0.0f) ? v3 : pa * v3;
            }
            *(__nv_bfloat162*)(Out + (size_t)row * DDIM + col) =
                __float22bfloat162_rn(make_float2(v0, v1));
            *(__nv_bfloat162*)(Out + (size_t)(row + 8) * DDIM + col) =
                __float22bfloat162_rn(make_float2(v2, v3));
        }
    }
}

// ---------------- row L2 normalization (bf16 in -> fp8 e4m3 out, x16) ------
__global__ __launch_bounds__(128) void l2norm_kernel()
{
    const __nv_bfloat16* h = blockIdx.y ? g_H16b : g_H16a;
    uint8_t* o8 = blockIdx.y ? g_b8 : g_a8;
    const int row = blockIdx.x;
    const int t = threadIdx.x;
    const __nv_bfloat162* src = (const __nv_bfloat162*)&h[(size_t)row * DDIM + t*4];
    __nv_bfloat162 h0 = src[0], h1 = src[1];
    float2 f0 = __bfloat1622float2(h0), f1 = __bfloat1622float2(h1);
    float ss = f0.x*f0.x + f0.y*f0.y + f1.x*f1.x + f1.y*f1.y;
    #pragma unroll
    for (int off = 16; off; off >>= 1) ss += __shfl_down_sync(0xffffffffu, ss, off);
    __shared__ float sm[4];
    __shared__ float stot;
    if ((t & 31) == 0) sm[t >> 5] = ss;
    __syncthreads();
    if (t == 0) stot = sm[0] + sm[1] + sm[2] + sm[3];
    __syncthreads();
    float scale = QSCL / fmaxf(sqrtf(stot), L2EPS);
    __nv_fp8x2_storage_t lo = __nv_cvt_float2_to_fp8x2(
        make_float2(f0.x * scale, f0.y * scale), __NV_SATFINITE, __NV_E4M3);
    __nv_fp8x2_storage_t hi = __nv_cvt_float2_to_fp8x2(
        make_float2(f1.x * scale, f1.y * scale), __NV_SATFINITE, __NV_E4M3);
    uint32_t packed = (uint32_t)lo | ((uint32_t)hi << 16);
    *(uint32_t*)(o8 + (size_t)row * DDIM + t * 4) = packed;
}

// ---------------- FP8 similarity kernel (512 thr, persistent I tiles) -------
__global__ __launch_bounds__(512, 1) void sim_kernel(const int* __restrict__ mask)
{
    extern __shared__ __align__(16) char dsm[];
    const uint32_t u0 = smem_u32(dsm);
    const uint32_t uRing = u0 + RING_OFF;
    float* sred = (float*)(dsm + SRED_OFF);   // 2048 floats

    const int t = threadIdx.x, w = t >> 5, lane = t & 31;
    const int rw = w & 7, ch = w >> 3;
    const int Ib = blockIdx.x, c = blockIdx.y;
    const int I = Ib * IT;
    const int Jbase = c * CHUNKJ;

    const int lr16 = lane & 15, lh = lane >> 4;
    const uint32_t aoff = (rw * 16 + lr16) * 144 + lh * 16;
    uint32_t boff[2];
    #pragma unroll
    for (int p = 0; p < 2; p++)
        boff[p] = ((ch * 2 + p) * 16 + lr16) * 144 + lh * 16;

    const int er = lane >> 2;
    const int ec = 2 * (lane & 3);
    const size_t gr0 = (size_t)(I + rw * 16 + er);

    // J-tile cp.async mapping: AJ/BJ each 512 chunks -> 1/thread
    const int rJ = t >> 3;
    const int cJ = (t & 7) * 16;
    const uint32_t dJ = rJ * 144 + cJ;

    float rs_aa0 = 0, rs_aa1 = 0, rm_aa0 = 0, rm_aa1 = 0;
    float rs_ab0 = 0, rs_ab1 = 0, rm_ab0 = 0, rm_ab1 = 0;

    float acc[3][4][4];
    #pragma unroll
    for (int m = 0; m < 3; m++)
        #pragma unroll
        for (int nb = 0; nb < 4; nb++)
            #pragma unroll
            for (int q = 0; q < 4; q++) acc[m][nb][q] = 0.0f;

    // ---- prologue: persistent I tiles (AI @0, BI @73728), 4 slabs each ----
    #pragma unroll
    for (int q = 0; q < 8; q++) {
        int id = t + q * 512;            // 0..4095
        int slab = id >> 10;             // 0..3
        int rem = id & 1023;
        int row = rem >> 3, c16 = (rem & 7) * 16;
        uint32_t dst = u0 + slab * 18432 + row * 144 + c16;
        const size_t gsrc = (size_t)(I + row) * DDIM + slab * 128 + c16;
        cpa16(dst, g_a8 + gsrc);
        cpa16(dst + 73728, g_b8 + gsrc);
    }
    CP_COMMIT();

    #define SIM_ISSUE(sidx)                                                     \
    do {                                                                        \
        const int _s = (sidx);                                                  \
        const uint32_t _b = uRing + (_s % 3) * RING_STAGE;                      \
        const int _J0 = Jbase + (_s >> 2) * 64;                                 \
        const int _kb = (_s & 3) * 128;                                         \
        const size_t _g = (size_t)(_J0 + rJ) * DDIM + _kb + cJ;                 \
        cpa16(_b + dJ, g_a8 + _g);                                              \
        cpa16(_b + 9216 + dJ, g_b8 + _g);                                       \
    } while (0)

    SIM_ISSUE(0); CP_COMMIT();
    SIM_ISSUE(1); CP_COMMIT();

    for (int s = 0; s < NSTAGE; s++) {
        cp_wait<1>();
        __syncthreads();
        if (s + 2 < NSTAGE) SIM_ISSUE(s + 2);
        CP_COMMIT();

        const uint32_t uAI = u0 + (s & 3) * 18432;
        const uint32_t uBI = uAI + 73728;
        const uint32_t uAJ = uRing + (s % 3) * RING_STAGE;
        const uint32_t uBJ = uAJ + 9216;
        #pragma unroll
        for (int ks = 0; ks < 4; ks++) {      // each ks = 32 fp8 k-elements
            uint32_t fA[4], fB[4], fJA[2][4], fJB[2][4];
            ldm4(fA, uAI + aoff + ks * 32);
            ldm4(fB, uBI + aoff + ks * 32);
            #pragma unroll
            for (int p = 0; p < 2; p++) {
                ldm4(fJA[p], uAJ + boff[p] + ks * 32);
                ldm4(fJB[p], uBJ + boff[p] + ks * 32);
            }
            #pragma unroll
            for (int p = 0; p < 2; p++) {
                mma_fp8(acc[0][2*p],   fA, fJA[p][0], fJA[p][2]);
                mma_fp8(acc[0][2*p+1], fA, fJA[p][1], fJA[p][3]);
                mma_fp8(acc[1][2*p],   fA, fJB[p][0], fJB[p][2]);
                mma_fp8(acc[1][2*p+1], fA, fJB[p][1], fJB[p][3]);
                mma_fp8(acc[2][2*p],   fB, fJB[p][0], fJB[p][2]);
                mma_fp8(acc[2][2*p+1], fB, fJB[p][1], fJB[p][3]);
            }
        }

        if ((s & 3) == 3) {
            const int J0 = Jbase + (s >> 2) * 64;
            #pragma unroll
            for (int nb = 0; nb < 4; nb++) {
                const int gc = J0 + (ch * 4 + nb) * 8 + ec;
                int2 m0 = *(const int2*)(mask + gr0 * NROWS + gc);
                int2 m1 = *(const int2*)(mask + (gr0 + 8) * NROWS + gc);
                float m00 = (float)m0.x, m01 = (float)m0.y;
                float m10 = (float)m1.x, m11 = (float)m1.y;

                float ea0 = __expf(acc[0][nb][0] * EXP_SCALE);
                float ea1 = __expf(acc[0][nb][1] * EXP_SCALE);
                float ea2 = __expf(acc[0][nb][2] * EXP_SCALE);
                float ea3 = __expf(acc[0][nb][3] * EXP_SCALE);
                float eb0 = __expf(acc[1][nb][0] * EXP_SCALE);
                float eb1 = __expf(acc[1][nb][1] * EXP_SCALE);
                float eb2 = __expf(acc[1][nb][2] * EXP_SCALE);
                float eb3 = __expf(acc[1][nb][3] * EXP_SCALE);
                float ec0 = __expf(acc[2][nb][0] * EXP_SCALE);
                float ec1 = __expf(acc[2][nb][1] * EXP_SCALE);
                float ec2 = __expf(acc[2][nb][2] * EXP_SCALE);
                float ec3 = __expf(acc[2][nb][3] * EXP_SCALE);

                rs_aa0 += ea0 + ea1;  rm_aa0 += ea0 * m00 + ea1 * m01;
                rs_aa1 += ea2 + ea3;  rm_aa1 += ea2 * m10 + ea3 * m11;
                rs_ab0 += eb0 + eb1;  rm_ab0 += eb0 * m00 + eb1 * m01;
                rs_ab1 += eb2 + eb3;  rm_ab1 += eb2 * m10 + eb3 * m11;

                float v[8];
                v[0] = eb0 + eb2;              v[1] = eb1 + eb3;
                v[2] = eb0 * m00 + eb2 * m10;  v[3] = eb1 * m01 + eb3 * m11;
                v[4] = ec0 + ec2;              v[5] = ec1 + ec3;
                v[6] = ec0 * m00 + ec2 * m10;  v[7] = ec1 * m01 + ec3 * m11;
                #pragma unroll
                for (int q = 0; q < 8; q++) {
                    v[q] += __shfl_down_sync(0xffffffffu, v[q], 16);
                    v[q] += __shfl_down_sync(0xffffffffu, v[q], 8);
                    v[q] += __shfl_down_sync(0xffffffffu, v[q], 4);
                }
                if (lane < 4) {
                    int cl = nb * 8 + 2 * lane;
                    sred[w * 128 + 0 * 32 + cl]     = v[0];
                    sred[w * 128 + 0 * 32 + cl + 1] = v[1];
                    sred[w * 128 + 1 * 32 + cl]     = v[2];
                    sred[w * 128 + 1 * 32 + cl + 1] = v[3];
                    sred[w * 128 + 2 * 32 + cl]     = v[4];
                    sred[w * 128 + 2 * 32 + cl + 1] = v[5];
                    sred[w * 128 + 3 * 32 + cl]     = v[6];
                    sred[w * 128 + 3 * 32 + cl + 1] = v[7];
                }
            }
            __syncthreads();
            if (t < 256) {
                int q = t >> 6, colg = t & 63;
                int ch2 = colg >> 5, cl = colg & 31;
                float sacc = 0.0f;
                #pragma unroll
                for (int r2 = 0; r2 < 8; r2++)
                    sacc += sred[(ch2 * 8 + r2) * 128 + q * 32 + cl];
                g_cp[q][Ib][J0 + colg] = sacc;
            }
            #pragma unroll
            for (int m = 0; m < 3; m++)
                #pragma unroll
                for (int nb = 0; nb < 4; nb++)
                    #pragma unroll
                    for (int q = 0; q < 4; q++) acc[m][nb][q] = 0.0f;
        }
    }

    #pragma unroll
    for (int d = 1; d < 4; d <<= 1) {
        rs_aa0 += __shfl_down_sync(0xffffffffu, rs_aa0, d, 4);
        rs_aa1 += __shfl_down_sync(0xffffffffu, rs_aa1, d, 4);
        rm_aa0 += __shfl_down_sync(0xffffffffu, rm_aa0, d, 4);
        rm_aa1 += __shfl_down_sync(0xffffffffu, rm_aa1, d, 4);
        rs_ab0 += __shfl_down_sync(0xffffffffu, rs_ab0, d, 4);
        rs_ab1 += __shfl_down_sync(0xffffffffu, rs_ab1, d, 4);
        rm_ab0 += __shfl_down_sync(0xffffffffu, rm_ab0, d, 4);
        rm_ab1 += __shfl_down_sync(0xffffffffu, rm_ab1, d, 4);
    }
    __syncthreads();
    const int r0 = rw * 16 + er;
    if (ch == 1 && (lane & 3) == 0) {
        sred[r0 * 4 + 0] = rs_aa0;  sred[r0 * 4 + 1] = rm_aa0;
        sred[r0 * 4 + 2] = rs_ab0;  sred[r0 * 4 + 3] = rm_ab0;
        sred[(r0 + 8) * 4 + 0] = rs_aa1;  sred[(r0 + 8) * 4 + 1] = rm_aa1;
        sred[(r0 + 8) * 4 + 2] = rs_ab1;  sred[(r0 + 8) * 4 + 3] = rm_ab1;
    }
    __syncthreads();
    if (ch == 0 && (lane & 3) == 0) {
        g_rp[c][0][I + r0]     = rs_aa0 + sred[r0 * 4 + 0];
        g_rp[c][1][I + r0]     = rm_aa0 + sred[r0 * 4 + 1];
        g_rp[c][2][I + r0]     = rs_ab0 + sred[r0 * 4 + 2];
        g_rp[c][3][I + r0]     = rm_ab0 + sred[r0 * 4 + 3];
        g_rp[c][0][I + r0 + 8] = rs_aa1 + sred[(r0 + 8) * 4 + 0];
        g_rp[c][1][I + r0 + 8] = rm_aa1 + sred[(r0 + 8) * 4 + 1];
        g_rp[c][2][I + r0 + 8] = rs_ab1 + sred[(r0 + 8) * 4 + 2];
        g_rp[c][3][I + r0 + 8] = rm_ab1 + sred[(r0 + 8) * 4 + 3];
    }
}

// ---------------- combine partials -> per-row losses ------------------------
__global__ __launch_bounds__(256) void rowloss2_kernel()
{
    int i = blockIdx.x * 256 + threadIdx.x;
    float aas = 0, aam = 0, abs_ = 0, abm = 0;
    #pragma unroll
    for (int c = 0; c < NCHUNK; c++) {
        aas  += g_rp[c][0][i];
        aam  += g_rp[c][1][i];
        abs_ += g_rp[c][2][i];
        abm  += g_rp[c][3][i];
    }
    float cabs = 0, cabm = 0, cbbs = 0, cbbm = 0;
    for (int b = 0; b < NIB; b++) {
        cabs += g_cp[0][b][i];
        cabm += g_cp[1][b][i];
        cbbs += g_cp[2][b][i];
        cbbm += g_cp[3][b][i];
    }
    g_rowloss[i]         = -logf(abm / (aas + abs_ - aam));
    g_rowloss[NROWS + i] = -logf(cabm / (cbbs + cabs - cbbm));
}

// ---------------- column-mean partials (readout s) --------------------------
__global__ __launch_bounds__(512) void colmean_kernel(const float* __restrict__ z1,
                                                      const float* __restrict__ z2)
{
    const float* z = blockIdx.y ? z2 : z1;
    const int rb = blockIdx.x;   // 16 row blocks of 256
    const int t = threadIdx.x;
    float a0 = 0, a1 = 0, a2 = 0, a3 = 0;
    const int r0 = rb * 256;
    for (int r = r0; r < r0 + 256; r += 4) {
        a0 += z[(size_t)(r+0) * DDIM + t];
        a1 += z[(size_t)(r+1) * DDIM + t];
        a2 += z[(size_t)(r+2) * DDIM + t];
        a3 += z[(size_t)(r+3) * DDIM + t];
    }
    g_smp[blockIdx.y][rb][t] = (a0 + a1 + a2 + a3) * (1.0f / NROWS);
}

// ---------------- global projector chain: summ_p = W @ proj(s_p) -----------
__device__ __forceinline__ void mv_stage(const float* __restrict__ Wm,
                                         const float* __restrict__ bias,
                                         const float* vin, float* vout,
                                         float pa, bool prelu_on,
                                         int warp, int lane)
{
    for (int rr = 0; rr < 32; rr++) {
        int o = warp * 32 + rr;
        const float* wr = Wm + (size_t)o * DDIM;
        float acc = 0.0f;
        for (int i = lane; i < DDIM; i += 32) acc += wr[i] * vin[i];
        #pragma unroll
        for (int off = 16; off; off >>= 1) acc += __shfl_down_sync(0xffffffffu, acc, off);
        if (lane == 0) {
            float v = acc + (bias ? bias[o] : 0.0f);
            if (prelu_on) v = (v >= 0.0f) ? v : pa * v;
            vout[o] = v;
        }
    }
}

__global__ __launch_bounds__(512) void gproj_kernel(
    const float* __restrict__ gw1, const float* __restrict__ gb1,
    const float* __restrict__ ga,  const float* __restrict__ gw2,
    const float* __restrict__ gb2, const float* __restrict__ W)
{
    __shared__ float v[DDIM], u[DDIM], hh[DDIM];
    const int p = blockIdx.x;
    const int t = threadIdx.x, warp = t >> 5, lane = t & 31;
    float sv = 0.0f;
    #pragma unroll
    for (int rb = 0; rb < 16; rb++) sv += g_smp[p][rb][t];
    v[t] = sv;
    __syncthreads();
    mv_stage(gw1, gb1, v, u, ga[0], true, warp, lane);
    __syncthreads();
    mv_stage(gw2, gb2, u, hh, 0.0f, false, warp, lane);
    __syncthreads();
    for (int rr = 0; rr < 32; rr++) {
        int o = warp * 32 + rr;
        const float* wr = W + (size_t)o * DDIM;
        float acc = 0.0f;
        for (int i = lane; i < DDIM; i += 32) acc += wr[i] * hh[i];
        #pragma unroll
        for (int off = 16; off; off >>= 1) acc += __shfl_down_sync(0xffffffffu, acc, off);
        if (lane == 0) g_summ[p * DDIM + o] = acc;
    }
}

// ---------------- per-row discriminator terms ------------------------------
__global__ __launch_bounds__(256) void sigrows_kernel(const float* __restrict__ z1,
                                                      const float* __restrict__ z2)
{
    const int warp = threadIdx.x >> 5, lane = threadIdx.x & 31;
    const int row = blockIdx.x * 8 + warp;
    const float* r1 = z1 + (size_t)row * DDIM;
    const float* r2 = z2 + (size_t)row * DDIM;
    float d11 = 0, d12 = 0, d21 = 0, d22 = 0;
    for (int i = lane; i < DDIM; i += 32) {
        float a = r1[i], b = r2[i];
        float s1 = g_summ[i], s2 = g_summ[DDIM + i];
        d11 += a * s1; d12 += a * s2; d21 += b * s1; d22 += b * s2;
    }
    #pragma unroll
    for (int off = 16; off; off >>= 1) {
        d11 += __shfl_down_sync(0xffffffffu, d11, off);
        d12 += __shfl_down_sync(0xffffffffu, d12, off);
        d21 += __shfl_down_sync(0xffffffffu, d21, off);
        d22 += __shfl_down_sync(0xffffffffu, d22, off);
    }
    if (lane == 0) {
        float sg11 = 1.0f / (1.0f + expf(-d11));
        float sg21 = 1.0f / (1.0f + expf(-d21));
        float sg22 = 1.0f / (1.0f + expf(-d22));
        float sg12 = 1.0f / (1.0f + expf(-d12));
        g_gl[0 * NROWS + row] = -logf(sg11 + EPS_);
        g_gl[1 * NROWS + row] = -logf(1.0f - sg21 + EPS_);
        g_gl[2 * NROWS + row] = -logf(sg22 + EPS_);
        g_gl[3 * NROWS + row] = -logf(1.0f - sg12 + EPS_);
    }
}

// ---------------- final deterministic reduction ----------------------------
__global__ __launch_bounds__(1024) void finalize_kernel(float* __restrict__ out)
{
    __shared__ float red[32];
    float acc[6] = {0, 0, 0, 0, 0, 0};
    for (int i = threadIdx.x; i < NROWS; i += 1024) {
        acc[0] += g_rowloss[i];
        acc[1] += g_rowloss[NROWS + i];
        acc[2] += g_gl[i];
        acc[3] += g_gl[NROWS + i];
        acc[4] += g_gl[2 * NROWS + i];
        acc[5] += g_gl[3 * NROWS + i];
    }
    const int lane = threadIdx.x & 31, warp = threadIdx.x >> 5;
    float tot[6];
    for (int q = 0; q < 6; q++) {
        float v = acc[q];
        #pragma unroll
        for (int off = 16; off; off >>= 1) v += __shfl_down_sync(0xffffffffu, v, off);
        if (lane == 0) red[warp] = v;
        __syncthreads();
        if (warp == 0) {
            float w = red[lane];
            #pragma unroll
            for (int off = 16; off; off >>= 1) w += __shfl_down_sync(0xffffffffu, w, off);
            if (lane == 0) tot[q] = w;
        }
        __syncthreads();
    }
    if (threadIdx.x == 0) {
        const float inv = 1.0f / NROWS;
        float local = 0.5f * (tot[0] + tot[1]) * inv;
        float gl1   = 0.5f * (tot[2] + tot[3]) * inv;
        float gl2   = 0.5f * (tot[4] + tot[5]) * inv;
        float glob  = 0.5f * (gl1 + gl2);
        out[0] = 0.5f * local + 0.5f * glob;   // ALPHA = 0.5
    }
}

// ---------------- launch ----------------------------------------------------
extern "C" void kernel_launch(void* const* d_in, const int* in_sizes, int n_in,
                              void* d_out, int out_size)
{
    const float* z1  = (const float*)d_in[0];
    const float* z2  = (const float*)d_in[1];
    const float* lw1 = (const float*)d_in[2];
    const float* lb1 = (const float*)d_in[3];
    const float* la  = (const float*)d_in[4];
    const float* lw2 = (const float*)d_in[5];
    const float* lb2 = (const float*)d_in[6];
    const float* gw1 = (const float*)d_in[7];
    const float* gb1 = (const float*)d_in[8];
    const float* ga  = (const float*)d_in[9];
    const float* gw2 = (const float*)d_in[10];
    const float* gb2 = (const float*)d_in[11];
    const float* W   = (const float*)d_in[12];
    const int*   mask= (const int*)  d_in[13];
    float* out = (float*)d_out;

    cudaFuncSetAttribute(sim_kernel, cudaFuncAttributeMaxDynamicSharedMemorySize,
                         SIM_SMEM_BYTES);
    cudaFuncSetAttribute(gemm_hmma_kernel, cudaFuncAttributeMaxDynamicSharedMemorySize,
                         GEMM_SMEM_BYTES);

    conv_all_kernel<<<2048, 256>>>(z1, z2, lw1, lw2);

    gemm_hmma_kernel<<<dim3(32, 4, 2), 256, GEMM_SMEM_BYTES>>>(lb1, la, 1);
    gemm_hmma_kernel<<<dim3(32, 4, 2), 256, GEMM_SMEM_BYTES>>>(lb2, nullptr, 2);

    l2norm_kernel<<<dim3(NROWS, 2), 128>>>();

    sim_kernel<<<dim3(NIB, NCHUNK), 512, SIM_SMEM_BYTES>>>(mask);
    rowloss2_kernel<<<NROWS / 256, 256>>>();

    colmean_kernel<<<dim3(16, 2), 512>>>(z1, z2);
    gproj_kernel<<<2, DDIM>>>(gw1, gb1, ga, gw2, gb2, W);
    sigrows_kernel<<<NROWS / 8, 256>>>(z1, z2);

    finalize_kernel<<<1, 1024>>>(out);
}

// round 16
// speedup vs baseline: 1.4948x; 1.0168x over previous
#include <cuda_runtime.h>
#include <cuda_bf16.h>
#include <cuda_fp8.h>
#include <math.h>
#include <cstdint>

#define NROWS 4096
#define DDIM  512
#define INV_TAU 5.0f
#define EXP_SCALE (INV_TAU / 256.0f)   // fp8 values scaled x16 -> dot x256
#define QSCL 16.0f
#define EPS_  1e-15f
#define L2EPS 1e-12f

#define IT 128
#define NIB (NROWS / IT)          // 32
#define NJT 64                    // J tiles of 64 per Ib
#define NTILE (NIB * NJT)         // 2048
#define NCTA 148

// sim kernel smem layout (bytes):
//   persistent I: AI 4 slabs @0 (4*18432), BI 4 slabs @73728
//   ring (3 stages x 18432): AJ @ +0, BJ @ +9216
//   sred after ring
#define RING_OFF  147456
#define RING_STAGE 18432
#define SRED_OFF  (RING_OFF + 3 * RING_STAGE)   // 202752
#define SIM_SMEM_BYTES (SRED_OFF + 8192)        // 210944

// gemm kernel: 3-stage ring of 32-wide bf16 k-slabs, row stride 80B
#define G_STAGE 20480
#define GEMM_SMEM_BYTES (3 * G_STAGE)

typedef unsigned long long u64;

// ---------------- scratch (static device allocations; no cudaMalloc) ------
__device__ __nv_bfloat16 g_z16a[NROWS * DDIM];
__device__ __nv_bfloat16 g_z16b[NROWS * DDIM];
__device__ __nv_bfloat16 g_T16a[NROWS * DDIM];
__device__ __nv_bfloat16 g_T16b[NROWS * DDIM];
__device__ __nv_bfloat16 g_H16a[NROWS * DDIM];
__device__ __nv_bfloat16 g_H16b[NROWS * DDIM];
__device__ __nv_bfloat16 g_w1s[DDIM * DDIM];
__device__ __nv_bfloat16 g_w2s[DDIM * DDIM];
__device__ uint8_t g_a8[NROWS * DDIM];   // fp8 e4m3, scaled x16
__device__ uint8_t g_b8[NROWS * DDIM];
__device__ float g_rowloss[2 * NROWS];
__device__ float g_gl[4 * NROWS];
__device__ float g_smp[2][16][DDIM];      // colmean partials
__device__ float g_summ[2 * DDIM];
__device__ float g_rpC[NCTA][2][4][IT];   // per-CTA-segment row partials
__device__ int   g_tagC[NCTA][2];         // segment Ib tags (-1 = unused)
__device__ float g_cp[4][NIB][NROWS];     // col partials: abS,abM,bbS,bbM

// ---------------- PTX helpers ----------------------------------------------
__device__ __forceinline__ uint32_t smem_u32(const void* p) {
    uint32_t a;
    asm("{ .reg .u64 tmp; cvta.to.shared.u64 tmp, %1; cvt.u32.u64 %0, tmp; }"
        : "=r"(a) : "l"(p));
    return a;
}

__device__ __forceinline__ void ldm4(uint32_t* r, uint32_t addr) {
    asm volatile("ldmatrix.sync.aligned.m8n8.x4.shared.b16 {%0,%1,%2,%3}, [%4];"
                 : "=r"(r[0]), "=r"(r[1]), "=r"(r[2]), "=r"(r[3]) : "r"(addr));
}

__device__ __forceinline__ void mma16816(float* c, const uint32_t* a,
                                         uint32_t b0, uint32_t b1) {
    asm volatile("mma.sync.aligned.m16n8k16.row.col.f32.bf16.bf16.f32 "
                 "{%0,%1,%2,%3}, {%4,%5,%6,%7}, {%8,%9}, {%0,%1,%2,%3};"
                 : "+f"(c[0]), "+f"(c[1]), "+f"(c[2]), "+f"(c[3])
                 : "r"(a[0]), "r"(a[1]), "r"(a[2]), "r"(a[3]), "r"(b0), "r"(b1));
}

__device__ __forceinline__ void mma_fp8(float* c, const uint32_t* a,
                                        uint32_t b0, uint32_t b1) {
    asm volatile("mma.sync.aligned.m16n8k32.row.col.f32.e4m3.e4m3.f32 "
                 "{%0,%1,%2,%3}, {%4,%5,%6,%7}, {%8,%9}, {%0,%1,%2,%3};"
                 : "+f"(c[0]), "+f"(c[1]), "+f"(c[2]), "+f"(c[3])
                 : "r"(a[0]), "r"(a[1]), "r"(a[2]), "r"(a[3]), "r"(b0), "r"(b1));
}

__device__ __forceinline__ void cpa16(uint32_t dst, const void* src) {
    asm volatile("cp.async.cg.shared.global [%0], [%1], 16;"
                 :: "r"(dst), "l"(src) : "memory");
}
#define CP_COMMIT() asm volatile("cp.async.commit_group;" ::: "memory")
template <int N>
__device__ __forceinline__ void cp_wait() {
    asm volatile("cp.async.wait_group %0;" :: "n"(N) : "memory");
}

// ---------------- fused fp32 -> bf16 conversion (all 4 arrays) -------------
#define Z4 (NROWS * DDIM / 4)      // 524288
#define W4 (DDIM * DDIM / 4)       // 65536
#define TOT4 (2 * Z4 + 2 * W4)

__global__ __launch_bounds__(256) void conv_all_kernel(
    const float* __restrict__ z1, const float* __restrict__ z2,
    const float* __restrict__ w1, const float* __restrict__ w2)
{
    for (int i = blockIdx.x * 256 + threadIdx.x; i < TOT4; i += gridDim.x * 256) {
        const float* src;
        __nv_bfloat16* dst;
        int o;
        if (i < Z4)            { src = z1; dst = g_z16a; o = i; }
        else if (i < 2 * Z4)   { src = z2; dst = g_z16b; o = i - Z4; }
        else if (i < 2*Z4+W4)  { src = w1; dst = g_w1s;  o = i - 2*Z4; }
        else                   { src = w2; dst = g_w2s;  o = i - 2*Z4 - W4; }
        float4 v = ((const float4*)src)[o];
        __nv_bfloat162* d = (__nv_bfloat162*)(dst + (size_t)o * 4);
        d[0] = __float22bfloat162_rn(make_float2(v.x, v.y));
        d[1] = __float22bfloat162_rn(make_float2(v.z, v.w));
    }
}

// ---------------- HMMA projector GEMM (256 threads, 3-stage ring, 2 CTA/SM) -
__global__ __launch_bounds__(256, 2) void gemm_hmma_kernel(
    const float* __restrict__ bias, const float* __restrict__ prelu_a, int stage)
{
    extern __shared__ __align__(16) char gsm[];
    const uint32_t u0 = smem_u32(gsm);

    const int t = threadIdx.x, w = t >> 5, lane = t & 31;
    const int I0 = blockIdx.x * 128, J0 = blockIdx.y * 128;
    const int z = blockIdx.z;

    const __nv_bfloat16* __restrict__ A =
        (stage == 1) ? (z ? g_z16b : g_z16a) : (z ? g_T16b : g_T16a);
    const __nv_bfloat16* __restrict__ Wm = (stage == 1) ? g_w1s : g_w2s;

    const int lr16 = lane & 15, lh = lane >> 4;
    const uint32_t aoff = (w * 16 + lr16) * 80 + lh * 16;
    uint32_t boff[8];
    #pragma unroll
    for (int p = 0; p < 8; p++)
        boff[p] = (p * 16 + lr16) * 80 + lh * 16;

    int rr[2], cc8[2];
    uint32_t dd[2];
    #pragma unroll
    for (int q = 0; q < 2; q++) {
        int id = t + q * 256;
        rr[q] = id >> 2; cc8[q] = (id & 3) * 8;
        dd[q] = rr[q] * 80 + (id & 3) * 16;
    }

    float acc[8][2][4];
    #pragma unroll
    for (int p = 0; p < 8; p++)
        #pragma unroll
        for (int h = 0; h < 2; h++)
            #pragma unroll
            for (int q = 0; q < 4; q++) acc[p][h][q] = 0.0f;

    #pragma unroll
    for (int s = 0; s < 2; s++) {
        const uint32_t b = u0 + s * G_STAGE;
        const int kb = s * 32;
        #pragma unroll
        for (int q = 0; q < 2; q++) {
            cpa16(b + dd[q], A + (size_t)(I0 + rr[q]) * DDIM + kb + cc8[q]);
            cpa16(b + 10240 + dd[q], Wm + (size_t)(J0 + rr[q]) * DDIM + kb + cc8[q]);
        }
        CP_COMMIT();
    }

    for (int ck = 0; ck < 16; ck++) {
        cp_wait<1>();
        __syncthreads();
        if (ck + 2 < 16) {
            const uint32_t b = u0 + ((ck + 2) % 3) * G_STAGE;
            const int kb = (ck + 2) * 32;
            #pragma unroll
            for (int q = 0; q < 2; q++) {
                cpa16(b + dd[q], A + (size_t)(I0 + rr[q]) * DDIM + kb + cc8[q]);
                cpa16(b + 10240 + dd[q], Wm + (size_t)(J0 + rr[q]) * DDIM + kb + cc8[q]);
            }
        }
        CP_COMMIT();
        const uint32_t uA = u0 + (ck % 3) * G_STAGE;
        const uint32_t uW = uA + 10240;
        #pragma unroll
        for (int ks = 0; ks < 2; ks++) {
            uint32_t fA[4];
            ldm4(fA, uA + aoff + ks * 32);
            #pragma unroll
            for (int p = 0; p < 8; p++) {
                uint32_t fW[4];
                ldm4(fW, uW + boff[p] + ks * 32);
                mma16816(acc[p][0], fA, fW[0], fW[2]);
                mma16816(acc[p][1], fA, fW[1], fW[3]);
            }
        }
    }

    const int er = lane >> 2, ec = 2 * (lane & 3);
    const int row = I0 + w * 16 + er;
    const bool do_prelu = (prelu_a != nullptr);
    const float pa = do_prelu ? prelu_a[0] : 0.0f;

    __nv_bfloat16* Out = (stage == 1) ? (z ? g_T16b : g_T16a)
                                      : (z ? g_H16b : g_H16a);
    #pragma unroll
    for (int p = 0; p < 8; p++) {
        #pragma unroll
        for (int h = 0; h < 2; h++) {
            int col = J0 + p * 16 + h * 8 + ec;
            float b0 = bias[col], b1 = bias[col + 1];
            float v0 = acc[p][h][0] + b0, v1 = acc[p][h][1] + b1;
            float v2 = acc[p][h][2] + b0, v3 = acc[p][h][3] + b1;
            if (do_prelu) {
                v0 = (v0 >= 0.0f) ? v0 : pa * v0;
                v1 = (v1 >= 0.0f) ? v1 : pa * v1;
                v2 = (v2 >= 0.0f) ? v2 : pa * v2;
                v3 = (v3 >= 0.0f) ? v3 : pa * v3;
            }
            *(__nv_bfloat162*)(Out + (size_t)row * DDIM + col) =
                __float22bfloat162_rn(make_float2(v0, v1));
            *(__nv_bfloat162*)(Out + (size_t)(row + 8) * DDIM + col) =
                __float22bfloat162_rn(make_float2(v2, v3));
        }
    }
}

// ---------------- row L2 normalization (bf16 in -> fp8 e4m3 out, x16) ------
__global__ __launch_bounds__(128) void l2norm_kernel()
{
    const __nv_bfloat16* h = blockIdx.y ? g_H16b : g_H16a;
    uint8_t* o8 = blockIdx.y ? g_b8 : g_a8;
    const int row = blockIdx.x;
    const int t = threadIdx.x;
    const __nv_bfloat162* src = (const __nv_bfloat162*)&h[(size_t)row * DDIM + t*4];
    __nv_bfloat162 h0 = src[0], h1 = src[1];
    float2 f0 = __bfloat1622float2(h0), f1 = __bfloat1622float2(h1);
    float ss = f0.x*f0.x + f0.y*f0.y + f1.x*f1.x + f1.y*f1.y;
    #pragma unroll
    for (int off = 16; off; off >>= 1) ss += __shfl_down_sync(0xffffffffu, ss, off);
    __shared__ float sm[4];
    __shared__ float stot;
    if ((t & 31) == 0) sm[t >> 5] = ss;
    __syncthreads();
    if (t == 0) stot = sm[0] + sm[1] + sm[2] + sm[3];
    __syncthreads();
    float scale = QSCL / fmaxf(sqrtf(stot), L2EPS);
    __nv_fp8x2_storage_t lo = __nv_cvt_float2_to_fp8x2(
        make_float2(f0.x * scale, f0.y * scale), __NV_SATFINITE, __NV_E4M3);
    __nv_fp8x2_storage_t hi = __nv_cvt_float2_to_fp8x2(
        make_float2(f1.x * scale, f1.y * scale), __NV_SATFINITE, __NV_E4M3);
    uint32_t packed = (uint32_t)lo | ((uint32_t)hi << 16);
    *(uint32_t*)(o8 + (size_t)row * DDIM + t * 4) = packed;
}

// ---------------- FP8 similarity kernel (148 CTAs, tile-scheduled) ----------
// Work item = tile (Ib, jt): I rows Ib*128..+127 vs J rows jt*64..+63.
// CTA k owns tiles [k*NTILE/NCTA, (k+1)*NTILE/NCTA) — <= 14 tiles, <= 2 Ibs.
__global__ __launch_bounds__(512, 1) void sim_kernel(const int* __restrict__ mask)
{
    extern __shared__ __align__(16) char dsm[];
    const uint32_t u0 = smem_u32(dsm);
    const uint32_t uRing = u0 + RING_OFF;
    float* sred = (float*)(dsm + SRED_OFF);   // 2048 floats

    const int t = threadIdx.x, w = t >> 5, lane = t & 31;
    const int rw = w & 7, ch = w >> 3;
    const int k = blockIdx.x;
    const int start = (k * NTILE) / NCTA;
    const int end   = ((k + 1) * NTILE) / NCTA;
    const int nslab = (end - start) * 4;

    const int lr16 = lane & 15, lh = lane >> 4;
    const uint32_t aoff = (rw * 16 + lr16) * 144 + lh * 16;
    uint32_t boff[2];
    #pragma unroll
    for (int p = 0; p < 2; p++)
        boff[p] = ((ch * 2 + p) * 16 + lr16) * 144 + lh * 16;

    const int er = lane >> 2;
    const int ec = 2 * (lane & 3);

    // J-tile cp.async mapping: AJ/BJ each 512 chunks -> 1/thread
    const int rJ = t >> 3;
    const int cJ = (t & 7) * 16;
    const uint32_t dJ = rJ * 144 + cJ;

    float rs_aa0 = 0, rs_aa1 = 0, rm_aa0 = 0, rm_aa1 = 0;
    float rs_ab0 = 0, rs_ab1 = 0, rm_ab0 = 0, rm_ab1 = 0;

    float acc[3][4][4];
    #pragma unroll
    for (int m = 0; m < 3; m++)
        #pragma unroll
        for (int nb = 0; nb < 4; nb++)
            #pragma unroll
            for (int q = 0; q < 4; q++) acc[m][nb][q] = 0.0f;

    #define LOAD_I(Ib_)                                                         \
    do {                                                                        \
        const int _I = (Ib_) * IT;                                              \
        _Pragma("unroll")                                                       \
        for (int q = 0; q < 8; q++) {                                           \
            int id = t + q * 512;                                               \
            int slab = id >> 10;                                                \
            int rem = id & 1023;                                                \
            int row = rem >> 3, c16 = (rem & 7) * 16;                           \
            uint32_t dst = u0 + slab * 18432 + row * 144 + c16;                 \
            const size_t gsrc = (size_t)(_I + row) * DDIM + slab * 128 + c16;   \
            cpa16(dst, g_a8 + gsrc);                                            \
            cpa16(dst + 73728, g_b8 + gsrc);                                    \
        }                                                                       \
        CP_COMMIT();                                                            \
    } while (0)

    #define SIM_ISSUE(sidx)                                                     \
    do {                                                                        \
        const int _s = (sidx);                                                  \
        const int _T = start + (_s >> 2);                                       \
        const int _J0 = (_T & 63) * 64;                                         \
        const int _kb = (_s & 3) * 128;                                         \
        const uint32_t _b = uRing + (_s % 3) * RING_STAGE;                      \
        const size_t _g = (size_t)(_J0 + rJ) * DDIM + _kb + cJ;                 \
        cpa16(_b + dJ, g_a8 + _g);                                              \
        cpa16(_b + 9216 + dJ, g_b8 + _g);                                       \
    } while (0)

    int cur_Ib = start >> 6;
    LOAD_I(cur_Ib);
    SIM_ISSUE(0); CP_COMMIT();
    SIM_ISSUE(1); CP_COMMIT();

    int slot = 0;
    int tag0 = -1, tag1 = -1;

    for (int s = 0; s < nslab; s++) {
        const int T = start + (s >> 2);
        const int Ib = T >> 6;

        cp_wait<1>();
        __syncthreads();
        if ((s & 3) == 0 && Ib != cur_Ib) {
            LOAD_I(Ib);
            cur_Ib = Ib;
            cp_wait<0>();
            __syncthreads();
        }
        if (s + 2 < nslab) SIM_ISSUE(s + 2);
        CP_COMMIT();

        const uint32_t uAI = u0 + (s & 3) * 18432;
        const uint32_t uBI = uAI + 73728;
        const uint32_t uAJ = uRing + (s % 3) * RING_STAGE;
        const uint32_t uBJ = uAJ + 9216;
        #pragma unroll
        for (int ks = 0; ks < 4; ks++) {      // each ks = 32 fp8 k-elements
            uint32_t fA[4], fB[4], fJA[2][4], fJB[2][4];
            ldm4(fA, uAI + aoff + ks * 32);
            ldm4(fB, uBI + aoff + ks * 32);
            #pragma unroll
            for (int p = 0; p < 2; p++) {
                ldm4(fJA[p], uAJ + boff[p] + ks * 32);
                ldm4(fJB[p], uBJ + boff[p] + ks * 32);
            }
            #pragma unroll
            for (int p = 0; p < 2; p++) {
                mma_fp8(acc[0][2*p],   fA, fJA[p][0], fJA[p][2]);
                mma_fp8(acc[0][2*p+1], fA, fJA[p][1], fJA[p][3]);
                mma_fp8(acc[1][2*p],   fA, fJB[p][0], fJB[p][2]);
                mma_fp8(acc[1][2*p+1], fA, fJB[p][1], fJB[p][3]);
                mma_fp8(acc[2][2*p],   fB, fJB[p][0], fJB[p][2]);
                mma_fp8(acc[2][2*p+1], fB, fJB[p][1], fJB[p][3]);
            }
        }

        if ((s & 3) == 3) {
            // ---- epilogue for tile T ----
            const int J0 = (T & 63) * 64;
            const size_t gr0 = (size_t)(Ib * IT + rw * 16 + er);
            #pragma unroll
            for (int nb = 0; nb < 4; nb++) {
                const int gc = J0 + (ch * 4 + nb) * 8 + ec;
                int2 m0 = *(const int2*)(mask + gr0 * NROWS + gc);
                int2 m1 = *(const int2*)(mask + (gr0 + 8) * NROWS + gc);
                float m00 = (float)m0.x, m01 = (float)m0.y;
                float m10 = (float)m1.x, m11 = (float)m1.y;

                float ea0 = __expf(acc[0][nb][0] * EXP_SCALE);
                float ea1 = __expf(acc[0][nb][1] * EXP_SCALE);
                float ea2 = __expf(acc[0][nb][2] * EXP_SCALE);
                float ea3 = __expf(acc[0][nb][3] * EXP_SCALE);
                float eb0 = __expf(acc[1][nb][0] * EXP_SCALE);
                float eb1 = __expf(acc[1][nb][1] * EXP_SCALE);
                float eb2 = __expf(acc[1][nb][2] * EXP_SCALE);
                float eb3 = __expf(acc[1][nb][3] * EXP_SCALE);
                float ec0 = __expf(acc[2][nb][0] * EXP_SCALE);
                float ec1 = __expf(acc[2][nb][1] * EXP_SCALE);
                float ec2 = __expf(acc[2][nb][2] * EXP_SCALE);
                float ec3 = __expf(acc[2][nb][3] * EXP_SCALE);

                rs_aa0 += ea0 + ea1;  rm_aa0 += ea0 * m00 + ea1 * m01;
                rs_aa1 += ea2 + ea3;  rm_aa1 += ea2 * m10 + ea3 * m11;
                rs_ab0 += eb0 + eb1;  rm_ab0 += eb0 * m00 + eb1 * m01;
                rs_ab1 += eb2 + eb3;  rm_ab1 += eb2 * m10 + eb3 * m11;

                float v[8];
                v[0] = eb0 + eb2;              v[1] = eb1 + eb3;
                v[2] = eb0 * m00 + eb2 * m10;  v[3] = eb1 * m01 + eb3 * m11;
                v[4] = ec0 + ec2;              v[5] = ec1 + ec3;
                v[6] = ec0 * m00 + ec2 * m10;  v[7] = ec1 * m01 + ec3 * m11;
                #pragma unroll
                for (int q = 0; q < 8; q++) {
                    v[q] += __shfl_down_sync(0xffffffffu, v[q], 16);
                    v[q] += __shfl_down_sync(0xffffffffu, v[q], 8);
                    v[q] += __shfl_down_sync(0xffffffffu, v[q], 4);
                }
                if (lane < 4) {
                    int cl = nb * 8 + 2 * lane;
                    sred[w * 128 + 0 * 32 + cl]     = v[0];
                    sred[w * 128 + 0 * 32 + cl + 1] = v[1];
                    sred[w * 128 + 1 * 32 + cl]     = v[2];
                    sred[w * 128 + 1 * 32 + cl + 1] = v[3];
                    sred[w * 128 + 2 * 32 + cl]     = v[4];
                    sred[w * 128 + 2 * 32 + cl + 1] = v[5];
                    sred[w * 128 + 3 * 32 + cl]     = v[6];
                    sred[w * 128 + 3 * 32 + cl + 1] = v[7];
                }
            }
            __syncthreads();
            if (t < 256) {
                int q = t >> 6, colg = t & 63;
                int ch2 = colg >> 5, cl = colg & 31;
                float sacc = 0.0f;
                #pragma unroll
                for (int r2 = 0; r2 < 8; r2++)
                    sacc += sred[(ch2 * 8 + r2) * 128 + q * 32 + cl];
                g_cp[q][Ib][J0 + colg] = sacc;
            }
            #pragma unroll
            for (int m = 0; m < 3; m++)
                #pragma unroll
                for (int nb = 0; nb < 4; nb++)
                    #pragma unroll
                    for (int q = 0; q < 4; q++) acc[m][nb][q] = 0.0f;

            // ---- segment flush (end of range or Ib boundary) ----
            bool lastTile = (s == nslab - 1);
            bool ibCross = !lastTile && (((T + 1) >> 6) != Ib);
            if (lastTile || ibCross) {
                #pragma unroll
                for (int d = 1; d < 4; d <<= 1) {
                    rs_aa0 += __shfl_down_sync(0xffffffffu, rs_aa0, d, 4);
                    rs_aa1 += __shfl_down_sync(0xffffffffu, rs_aa1, d, 4);
                    rm_aa0 += __shfl_down_sync(0xffffffffu, rm_aa0, d, 4);
                    rm_aa1 += __shfl_down_sync(0xffffffffu, rm_aa1, d, 4);
                    rs_ab0 += __shfl_down_sync(0xffffffffu, rs_ab0, d, 4);
                    rs_ab1 += __shfl_down_sync(0xffffffffu, rs_ab1, d, 4);
                    rm_ab0 += __shfl_down_sync(0xffffffffu, rm_ab0, d, 4);
                    rm_ab1 += __shfl_down_sync(0xffffffffu, rm_ab1, d, 4);
                }
                __syncthreads();   // g_cp reads of sred done before reuse
                const int r0 = rw * 16 + er;
                if (ch == 1 && (lane & 3) == 0) {
                    sred[r0 * 4 + 0] = rs_aa0;  sred[r0 * 4 + 1] = rm_aa0;
                    sred[r0 * 4 + 2] = rs_ab0;  sred[r0 * 4 + 3] = rm_ab0;
                    sred[(r0 + 8) * 4 + 0] = rs_aa1;  sred[(r0 + 8) * 4 + 1] = rm_aa1;
                    sred[(r0 + 8) * 4 + 2] = rs_ab1;  sred[(r0 + 8) * 4 + 3] = rm_ab1;
                }
                __syncthreads();
                if (ch == 0 && (lane & 3) == 0) {
                    g_rpC[k][slot][0][r0]     = rs_aa0 + sred[r0 * 4 + 0];
                    g_rpC[k][slot][1][r0]     = rm_aa0 + sred[r0 * 4 + 1];
                    g_rpC[k][slot][2][r0]     = rs_ab0 + sred[r0 * 4 + 2];
                    g_rpC[k][slot][3][r0]     = rm_ab0 + sred[r0 * 4 + 3];
                    g_rpC[k][slot][0][r0 + 8] = rs_aa1 + sred[(r0 + 8) * 4 + 0];
                    g_rpC[k][slot][1][r0 + 8] = rm_aa1 + sred[(r0 + 8) * 4 + 1];
                    g_rpC[k][slot][2][r0 + 8] = rs_ab1 + sred[(r0 + 8) * 4 + 2];
                    g_rpC[k][slot][3][r0 + 8] = rm_ab1 + sred[(r0 + 8) * 4 + 3];
                }
                if (slot == 0) tag0 = Ib; else tag1 = Ib;
                slot++;
                rs_aa0 = rs_aa1 = rm_aa0 = rm_aa1 = 0.0f;
                rs_ab0 = rs_ab1 = rm_ab0 = rm_ab1 = 0.0f;
            }
        }
    }

    if (t == 0) {
        g_tagC[k][0] = tag0;
        g_tagC[k][1] = tag1;
    }
}

// ---------------- combine partials -> per-row losses ------------------------
__global__ __launch_bounds__(256) void rowloss2_kernel()
{
    int i = blockIdx.x * 256 + threadIdx.x;
    const int myIb = i >> 7;
    const int lr = i & 127;
    float aas = 0, aam = 0, abs_ = 0, abm = 0;
    for (int kk = 0; kk < NCTA; kk++) {
        #pragma unroll
        for (int sl = 0; sl < 2; sl++) {
            if (g_tagC[kk][sl] == myIb) {
                aas  += g_rpC[kk][sl][0][lr];
                aam  += g_rpC[kk][sl][1][lr];
                abs_ += g_rpC[kk][sl][2][lr];
                abm  += g_rpC[kk][sl][3][lr];
            }
        }
    }
    float cabs = 0, cabm = 0, cbbs = 0, cbbm = 0;
    for (int b = 0; b < NIB; b++) {
        cabs += g_cp[0][b][i];
        cabm += g_cp[1][b][i];
        cbbs += g_cp[2][b][i];
        cbbm += g_cp[3][b][i];
    }
    g_rowloss[i]         = -logf(abm / (aas + abs_ - aam));
    g_rowloss[NROWS + i] = -logf(cabm / (cbbs + cabs - cbbm));
}

// ---------------- column-mean partials (readout s) --------------------------
__global__ __launch_bounds__(512) void colmean_kernel(const float* __restrict__ z1,
                                                      const float* __restrict__ z2)
{
    const float* z = blockIdx.y ? z2 : z1;
    const int rb = blockIdx.x;   // 16 row blocks of 256
    const int t = threadIdx.x;
    float a0 = 0, a1 = 0, a2 = 0, a3 = 0;
    const int r0 = rb * 256;
    for (int r = r0; r < r0 + 256; r += 4) {
        a0 += z[(size_t)(r+0) * DDIM + t];
        a1 += z[(size_t)(r+1) * DDIM + t];
        a2 += z[(size_t)(r+2) * DDIM + t];
        a3 += z[(size_t)(r+3) * DDIM + t];
    }
    g_smp[blockIdx.y][rb][t] = (a0 + a1 + a2 + a3) * (1.0f / NROWS);
}

// ---------------- global projector chain: summ_p = W @ proj(s_p) -----------
__device__ __forceinline__ void mv_stage(const float* __restrict__ Wm,
                                         const float* __restrict__ bias,
                                         const float* vin, float* vout,
                                         float pa, bool prelu_on,
                                         int warp, int lane)
{
    for (int rr = 0; rr < 32; rr++) {
        int o = warp * 32 + rr;
        const float* wr = Wm + (size_t)o * DDIM;
        float acc = 0.0f;
        for (int i = lane; i < DDIM; i += 32) acc += wr[i] * vin[i];
        #pragma unroll
        for (int off = 16; off; off >>= 1) acc += __shfl_down_sync(0xffffffffu, acc, off);
        if (lane == 0) {
            float v = acc + (bias ? bias[o] : 0.0f);
            if (prelu_on) v = (v >= 0.0f) ? v : pa * v;
            vout[o] = v;
        }
    }
}

__global__ __launch_bounds__(512) void gproj_kernel(
    const float* __restrict__ gw1, const float* __restrict__ gb1,
    const float* __restrict__ ga,  const float* __restrict__ gw2,
    const float* __restrict__ gb2, const float* __restrict__ W)
{
    __shared__ float v[DDIM], u[DDIM], hh[DDIM];
    const int p = blockIdx.x;
    const int t = threadIdx.x, warp = t >> 5, lane = t & 31;
    float sv = 0.0f;
    #pragma unroll
    for (int rb = 0; rb < 16; rb++) sv += g_smp[p][rb][t];
    v[t] = sv;
    __syncthreads();
    mv_stage(gw1, gb1, v, u, ga[0], true, warp, lane);
    __syncthreads();
    mv_stage(gw2, gb2, u, hh, 0.0f, false, warp, lane);
    __syncthreads();
    for (int rr = 0; rr < 32; rr++) {
        int o = warp * 32 + rr;
        const float* wr = W + (size_t)o * DDIM;
        float acc = 0.0f;
        for (int i = lane; i < DDIM; i += 32) acc += wr[i] * hh[i];
        #pragma unroll
        for (int off = 16; off; off >>= 1) acc += __shfl_down_sync(0xffffffffu, acc, off);
        if (lane == 0) g_summ[p * DDIM + o] = acc;
    }
}

// ---------------- per-row discriminator terms ------------------------------
__global__ __launch_bounds__(256) void sigrows_kernel(const float* __restrict__ z1,
                                                      const float* __restrict__ z2)
{
    const int warp = threadIdx.x >> 5, lane = threadIdx.x & 31;
    const int row = blockIdx.x * 8 + warp;
    const float* r1 = z1 + (size_t)row * DDIM;
    const float* r2 = z2 + (size_t)row * DDIM;
    float d11 = 0, d12 = 0, d21 = 0, d22 = 0;
    for (int i = lane; i < DDIM; i += 32) {
        float a = r1[i], b = r2[i];
        float s1 = g_summ[i], s2 = g_summ[DDIM + i];
        d11 += a * s1; d12 += a * s2; d21 += b * s1; d22 += b * s2;
    }
    #pragma unroll
    for (int off = 16; off; off >>= 1) {
        d11 += __shfl_down_sync(0xffffffffu, d11, off);
        d12 += __shfl_down_sync(0xffffffffu, d12, off);
        d21 += __shfl_down_sync(0xffffffffu, d21, off);
        d22 += __shfl_down_sync(0xffffffffu, d22, off);
    }
    if (lane == 0) {
        float sg11 = 1.0f / (1.0f + expf(-d11));
        float sg21 = 1.0f / (1.0f + expf(-d21));
        float sg22 = 1.0f / (1.0f + expf(-d22));
        float sg12 = 1.0f / (1.0f + expf(-d12));
        g_gl[0 * NROWS + row] = -logf(sg11 + EPS_);
        g_gl[1 * NROWS + row] = -logf(1.0f - sg21 + EPS_);
        g_gl[2 * NROWS + row] = -logf(sg22 + EPS_);
        g_gl[3 * NROWS + row] = -logf(1.0f - sg12 + EPS_);
    }
}

// ---------------- final deterministic reduction ----------------------------
__global__ __launch_bounds__(1024) void finalize_kernel(float* __restrict__ out)
{
    __shared__ float red[32];
    float acc[6] = {0, 0, 0, 0, 0, 0};
    for (int i = threadIdx.x; i < NROWS; i += 1024) {
        acc[0] += g_rowloss[i];
        acc[1] += g_rowloss[NROWS + i];
        acc[2] += g_gl[i];
        acc[3] += g_gl[NROWS + i];
        acc[4] += g_gl[2 * NROWS + i];
        acc[5] += g_gl[3 * NROWS + i];
    }
    const int lane = threadIdx.x & 31, warp = threadIdx.x >> 5;
    float tot[6];
    for (int q = 0; q < 6; q++) {
        float v = acc[q];
        #pragma unroll
        for (int off = 16; off; off >>= 1) v += __shfl_down_sync(0xffffffffu, v, off);
        if (lane == 0) red[warp] = v;
        __syncthreads();
        if (warp == 0) {
            float w = red[lane];
            #pragma unroll
            for (int off = 16; off; off >>= 1) w += __shfl_down_sync(0xffffffffu, w, off);
            if (lane == 0) tot[q] = w;
        }
        __syncthreads();
    }
    if (threadIdx.x == 0) {
        const float inv = 1.0f / NROWS;
        float local = 0.5f * (tot[0] + tot[1]) * inv;
        float gl1   = 0.5f * (tot[2] + tot[3]) * inv;
        float gl2   = 0.5f * (tot[4] + tot[5]) * inv;
        float glob  = 0.5f * (gl1 + gl2);
        out[0] = 0.5f * local + 0.5f * glob;   // ALPHA = 0.5
    }
}

// ---------------- launch ----------------------------------------------------
extern "C" void kernel_launch(void* const* d_in, const int* in_sizes, int n_in,
                              void* d_out, int out_size)
{
    const float* z1  = (const float*)d_in[0];
    const float* z2  = (const float*)d_in[1];
    const float* lw1 = (const float*)d_in[2];
    const float* lb1 = (const float*)d_in[3];
    const float* la  = (const float*)d_in[4];
    const float* lw2 = (const float*)d_in[5];
    const float* lb2 = (const float*)d_in[6];
    const float* gw1 = (const float*)d_in[7];
    const float* gb1 = (const float*)d_in[8];
    const float* ga  = (const float*)d_in[9];
    const float* gw2 = (const float*)d_in[10];
    const float* gb2 = (const float*)d_in[11];
    const float* W   = (const float*)d_in[12];
    const int*   mask= (const int*)  d_in[13];
    float* out = (float*)d_out;

    cudaFuncSetAttribute(sim_kernel, cudaFuncAttributeMaxDynamicSharedMemorySize,
                         SIM_SMEM_BYTES);
    cudaFuncSetAttribute(gemm_hmma_kernel, cudaFuncAttributeMaxDynamicSharedMemorySize,
                         GEMM_SMEM_BYTES);

    conv_all_kernel<<<2048, 256>>>(z1, z2, lw1, lw2);

    gemm_hmma_kernel<<<dim3(32, 4, 2), 256, GEMM_SMEM_BYTES>>>(lb1, la, 1);
    gemm_hmma_kernel<<<dim3(32, 4, 2), 256, GEMM_SMEM_BYTES>>>(lb2, nullptr, 2);

    l2norm_kernel<<<dim3(NROWS, 2), 128>>>();

    sim_kernel<<<NCTA, 512, SIM_SMEM_BYTES>>>(mask);
    rowloss2_kernel<<<NROWS / 256, 256>>>();

    colmean_kernel<<<dim3(16, 2), 512>>>(z1, z2);
    gproj_kernel<<<2, DDIM>>>(gw1, gb1, ga, gw2, gb2, W);
    sigrows_kernel<<<NROWS / 8, 256>>>(z1, z2);

    finalize_kernel<<<1, 1024>>>(out);
}